// round 6
// baseline (speedup 1.0000x reference)
#include <cuda_runtime.h>

#define NN 100000
#define NE 3200000
#define NG 64
#define NWARPS (592 * 8)
#define EPS 1e-5f

// __device__ scratch (allocation-free rule). Accumulators that persist across
// graph replays are reset by the last kernel that reads them.
__device__ float4 d_xn[NN];    // overwritten each run
__device__ float4 d_y[NN];     // overwritten each run
__device__ float4 d_a1[NN];    // z = dinv*a1 (overwritten, no reset needed)
__device__ float  d_dinv[NN];  // overwritten
__device__ int    d_degi[NN];  // atomic-counted; reset in k_conv2
__device__ int    d_ptr[NN];   // overwritten by scan
__device__ int    d_cur[NN];   // overwritten by scan
__device__ int    d_csr[NE];   // fully overwritten by build
__device__ double d_sum[4];    // atomic; reset in k_conv1
__device__ double d_sumsq[4];  // atomic; reset in k_conv1
__device__ float  d_acc[NG * 8]; // per graph: [0..3]=s4,[4]=ss,[5]=ng; reset in k_final

__device__ __forceinline__ void red1(float* p, float a) {
    asm volatile("red.global.add.f32 [%0], %1;" :: "l"(p), "f"(a) : "memory");
}

// deg count (int atomics, 4 edges/thread) + BN0 stats
__global__ void k_pre(const float* __restrict__ x, const int* __restrict__ ei) {
    int t = blockIdx.x * blockDim.x + threadIdx.x;
    if (t < NE / 4) {
        int4 d = ((const int4*)(ei + NE))[t];
        atomicAdd(&d_degi[d.x], 1);
        atomicAdd(&d_degi[d.y], 1);
        atomicAdd(&d_degi[d.z], 1);
        atomicAdd(&d_degi[d.w], 1);
    }
    if (blockIdx.x < 256) {
        int j0 = blockIdx.x * blockDim.x + threadIdx.x;
        int stride = 256 * blockDim.x;
        double s0 = 0, s1 = 0, s2 = 0, s3 = 0;
        double q0 = 0, q1 = 0, q2 = 0, q3 = 0;
        for (int j = j0; j < NN; j += stride) {
            float4 v = ((const float4*)x)[j];
            s0 += v.x; q0 += (double)v.x * v.x;
            s1 += v.y; q1 += (double)v.y * v.y;
            s2 += v.z; q2 += (double)v.z * v.z;
            s3 += v.w; q3 += (double)v.w * v.w;
        }
        #pragma unroll
        for (int o = 16; o > 0; o >>= 1) {
            s0 += __shfl_down_sync(0xffffffffu, s0, o);
            s1 += __shfl_down_sync(0xffffffffu, s1, o);
            s2 += __shfl_down_sync(0xffffffffu, s2, o);
            s3 += __shfl_down_sync(0xffffffffu, s3, o);
            q0 += __shfl_down_sync(0xffffffffu, q0, o);
            q1 += __shfl_down_sync(0xffffffffu, q1, o);
            q2 += __shfl_down_sync(0xffffffffu, q2, o);
            q3 += __shfl_down_sync(0xffffffffu, q3, o);
        }
        if ((threadIdx.x & 31) == 0) {
            atomicAdd(&d_sum[0], s0); atomicAdd(&d_sumsq[0], q0);
            atomicAdd(&d_sum[1], s1); atomicAdd(&d_sumsq[1], q1);
            atomicAdd(&d_sum[2], s2); atomicAdd(&d_sumsq[2], q2);
            atomicAdd(&d_sum[3], s3); atomicAdd(&d_sumsq[3], q3);
        }
    }
}

// Single-block exclusive prefix sum of deg -> d_ptr, d_cur
__global__ void k_scan() {
    __shared__ int part[1024];
    const int C = (NN + 1023) / 1024;  // 98
    int t = threadIdx.x;
    int base = t * C;
    int s = 0;
    for (int j = 0; j < C; j++) {
        int i = base + j;
        if (i < NN) s += d_degi[i];
    }
    part[t] = s;
    __syncthreads();
    // Hillis-Steele inclusive scan
    for (int o = 1; o < 1024; o <<= 1) {
        int v = (t >= o) ? part[t - o] : 0;
        __syncthreads();
        part[t] += v;
        __syncthreads();
    }
    int run = (t == 0) ? 0 : part[t - 1];
    for (int j = 0; j < C; j++) {
        int i = base + j;
        if (i < NN) {
            d_ptr[i] = run;
            d_cur[i] = run;
            run += d_degi[i];
        }
    }
}

// Fused: CSR build (scatter src into dst buckets) + node1 (BN0, dinv, y)
__global__ void k_build(const int* __restrict__ ei,
                        const float* __restrict__ x,
                        const float* __restrict__ g0,
                        const float* __restrict__ b0) {
    __shared__ float sbn[12];
    int gid = blockIdx.x * blockDim.x + threadIdx.x;
    if ((int)(blockIdx.x * blockDim.x) < NN) {
        if (threadIdx.x == 0) {
            #pragma unroll
            for (int c = 0; c < 4; c++) {
                double m = d_sum[c] / (double)NN;
                double var = d_sumsq[c] / (double)NN - m * m;
                sbn[c] = (float)m;
                sbn[4 + c] = rsqrtf((float)var + EPS) * g0[c];
                sbn[8 + c] = b0[c];
            }
        }
        __syncthreads();
        if (gid < NN) {
            float4 v = ((const float4*)x)[gid];
            float4 o;
            o.x = (v.x - sbn[0]) * sbn[4] + sbn[8];
            o.y = (v.y - sbn[1]) * sbn[5] + sbn[9];
            o.z = (v.z - sbn[2]) * sbn[6] + sbn[10];
            o.w = (v.w - sbn[3]) * sbn[7] + sbn[11];
            d_xn[gid] = o;
            float di = rsqrtf((float)d_degi[gid] + 1.0f);
            d_dinv[gid] = di;
            float4 y;
            y.x = o.x * di; y.y = o.y * di; y.z = o.z * di; y.w = o.w * di;
            d_y[gid] = y;
        }
    }
    if (gid < NE / 4) {
        int4 s = ((const int4*)ei)[gid];
        int4 d = ((const int4*)(ei + NE))[gid];
        int p0 = atomicAdd(&d_cur[d.x], 1); d_csr[p0] = s.x;
        int p1 = atomicAdd(&d_cur[d.y], 1); d_csr[p1] = s.y;
        int p2 = atomicAdd(&d_cur[d.z], 1); d_csr[p2] = s.z;
        int p3 = atomicAdd(&d_cur[d.w], 1); d_csr[p3] = s.w;
    }
}

// conv1 gather (warp per node, grid-stride) + node2 fold: z = di^2*agg + di^3*xn
__global__ void __launch_bounds__(256) k_conv1() {
    if (blockIdx.x == 0 && threadIdx.x < 4) {
        d_sum[threadIdx.x] = 0.0;
        d_sumsq[threadIdx.x] = 0.0;
    }
    int gw = (blockIdx.x * blockDim.x + threadIdx.x) >> 5;
    int lane = threadIdx.x & 31;
    for (int i = gw; i < NN; i += NWARPS) {
        int start = d_ptr[i];
        int end = start + d_degi[i];
        float ax = 0.f, ay = 0.f, az = 0.f, aw = 0.f;
        for (int e = start + lane; e < end; e += 32) {
            float4 y = d_y[d_csr[e]];
            ax += y.x; ay += y.y; az += y.z; aw += y.w;
        }
        #pragma unroll
        for (int o = 16; o > 0; o >>= 1) {
            ax += __shfl_down_sync(0xffffffffu, ax, o);
            ay += __shfl_down_sync(0xffffffffu, ay, o);
            az += __shfl_down_sync(0xffffffffu, az, o);
            aw += __shfl_down_sync(0xffffffffu, aw, o);
        }
        if (lane == 0) {
            float di = d_dinv[i];
            float di2 = di * di;
            float di3 = di2 * di;
            float4 xv = d_xn[i];
            float4 z;
            z.x = ax * di2 + xv.x * di3;
            z.y = ay * di2 + xv.y * di3;
            z.z = az * di2 + xv.z * di3;
            z.w = aw * di2 + xv.w * di3;
            d_a1[i] = z;
        }
    }
}

// conv2 gather (warp per node) + node3 fold: per-graph accumulation
__global__ void __launch_bounds__(256) k_conv2(const int* __restrict__ batch) {
    __shared__ float sacc[NG * 6];
    for (int j = threadIdx.x; j < NG * 6; j += blockDim.x) sacc[j] = 0.f;
    __syncthreads();
    int gw = (blockIdx.x * blockDim.x + threadIdx.x) >> 5;
    int lane = threadIdx.x & 31;
    for (int i = gw; i < NN; i += NWARPS) {
        int start = d_ptr[i];
        int degx = d_degi[i];
        int end = start + degx;
        float mx = 0.f, my = 0.f, mz = 0.f, mw = 0.f, n = 0.f;
        for (int e = start + lane; e < end; e += 32) {
            int s = d_csr[e];
            float4 z = d_a1[s];
            mx += z.x; my += z.y; mz += z.z; mw += z.w;
            n += d_dinv[s];
        }
        #pragma unroll
        for (int o = 16; o > 0; o >>= 1) {
            mx += __shfl_down_sync(0xffffffffu, mx, o);
            my += __shfl_down_sync(0xffffffffu, my, o);
            mz += __shfl_down_sync(0xffffffffu, mz, o);
            mw += __shfl_down_sync(0xffffffffu, mw, o);
            n  += __shfl_down_sync(0xffffffffu, n, o);
        }
        if (lane == 0) {
            d_degi[i] = 0;   // reset for next replay
            float di = d_dinv[i];
            float4 z = d_a1[i];
            int g = batch[i];
            float* p = &sacc[g * 6];
            atomicAdd(p + 0, di * (mx + z.x));
            atomicAdd(p + 1, di * (my + z.y));
            atomicAdd(p + 2, di * (mz + z.z));
            atomicAdd(p + 3, di * (mw + z.w));
            atomicAdd(p + 4, di * (n + di));
            atomicAdd(p + 5, 1.0f);
        }
    }
    __syncthreads();
    for (int j = threadIdx.x; j < NG * 6; j += blockDim.x) {
        int g = j / 6, c = j % 6;
        red1(&d_acc[g * 8 + c], sacc[j]);
    }
}

// One block, 64 threads: W0/W1 apply, BN1 over graphs, MLP; resets d_acc
__global__ void k_final(const float* __restrict__ W0, const float* __restrict__ b0,
                        const float* __restrict__ W1, const float* __restrict__ b1,
                        const float* __restrict__ bn1g, const float* __restrict__ bn1b,
                        const float* __restrict__ l0W, const float* __restrict__ l0b,
                        const float* __restrict__ l1W, const float* __restrict__ l1b,
                        const float* __restrict__ oW, const float* __restrict__ ob,
                        float* __restrict__ out) {
    __shared__ float sg[64][65];
    __shared__ float sW[64 * 64];
    int t = threadIdx.x;

    for (int j = t; j < 4096; j += 64) sW[j] = W1[j];

    float* acc = &d_acc[t * 8];
    float s4[4];
    #pragma unroll
    for (int c = 0; c < 4; c++) s4[c] = acc[c];
    float ss = acc[4];
    float ng = acc[5];
    #pragma unroll
    for (int c = 0; c < 8; c++) acc[c] = 0.f;

    float h[64];
    #pragma unroll
    for (int j = 0; j < 64; j++)
        h[j] = ss * b0[j] + s4[0] * W0[j] + s4[1] * W0[64 + j]
             + s4[2] * W0[128 + j] + s4[3] * W0[192 + j];
    __syncthreads();

    for (int j = 0; j < 64; j++) {
        float a = ng * b1[j];
        #pragma unroll
        for (int k = 0; k < 64; k++) a += h[k] * sW[k * 64 + j];
        sg[t][j] = a;
    }
    __syncthreads();

    {
        float m = 0.f;
        for (int G = 0; G < 64; G++) m += sg[G][t];
        m *= (1.0f / 64.0f);
        float v = 0.f;
        for (int G = 0; G < 64; G++) { float d = sg[G][t] - m; v += d * d; }
        v *= (1.0f / 64.0f);
        float r = rsqrtf(v + EPS) * bn1g[t];
        float bb = bn1b[t];
        for (int G = 0; G < 64; G++) sg[G][t] = (sg[G][t] - m) * r + bb;
    }
    __syncthreads();

    float h2[64];
    #pragma unroll
    for (int k = 0; k < 64; k++) h2[k] = sg[t][k];
    __syncthreads();
    for (int j = t; j < 4096; j += 64) sW[j] = l0W[j];
    __syncthreads();
    for (int j = 0; j < 64; j++) {
        float a = l0b[j];
        #pragma unroll
        for (int k = 0; k < 64; k++) a += h2[k] * sW[k * 64 + j];
        sg[t][j] = a;
    }
    __syncthreads();

    #pragma unroll
    for (int k = 0; k < 64; k++) h2[k] = sg[t][k];
    __syncthreads();
    for (int j = t; j < 4096; j += 64) sW[j] = l1W[j];
    __syncthreads();
    float o = ob[0];
    for (int j = 0; j < 64; j++) {
        float a = l1b[j];
        #pragma unroll
        for (int k = 0; k < 64; k++) a += h2[k] * sW[k * 64 + j];
        o += a * oW[j];
    }
    out[t] = o;
}

extern "C" void kernel_launch(void* const* d_in, const int* in_sizes, int n_in,
                              void* d_out, int out_size) {
    const float* x     = (const float*)d_in[0];
    const int*   ei    = (const int*)d_in[1];
    const int*   batch = (const int*)d_in[2];
    const float* bn0g = (const float*)d_in[3];
    const float* bn0b = (const float*)d_in[4];
    const float* W0   = (const float*)d_in[5];
    const float* b0   = (const float*)d_in[6];
    const float* W1   = (const float*)d_in[7];
    const float* b1   = (const float*)d_in[8];
    const float* bn1g = (const float*)d_in[9];
    const float* bn1b = (const float*)d_in[10];
    const float* l0W  = (const float*)d_in[11];
    const float* l0b  = (const float*)d_in[12];
    const float* l1W  = (const float*)d_in[13];
    const float* l1b  = (const float*)d_in[14];
    const float* oW   = (const float*)d_in[15];
    const float* ob   = (const float*)d_in[16];
    float* out = (float*)d_out;

    int ethreads = NE / 4;  // 800K
    k_pre  <<<(ethreads + 255) / 256, 256>>>(x, ei);
    k_scan <<<1, 1024>>>();
    k_build<<<(ethreads + 255) / 256, 256>>>(ei, x, bn0g, bn0b);
    k_conv1<<<592, 256>>>();
    k_conv2<<<592, 256>>>(batch);
    k_final<<<1, 64>>>(W0, b0, W1, b1, bn1g, bn1b,
                       l0W, l0b, l1W, l1b, oW, ob, out);
}

// round 8
// speedup vs baseline: 1.7125x; 1.7125x over previous
#include <cuda_runtime.h>

#define NN 100000
#define NE 3200000
#define NG 64
#define EPS 1e-5f

// Scratch (__device__ globals; accumulators are zero at rest — each kernel
// that last reads one resets it for the next graph replay).
__device__ float4 d_xn[NN];     // overwritten each run
__device__ float4 d_y[NN];      // overwritten each run
__device__ float4 d_a1[NN];     // raw agg, then z (accumulator; reset in node3)
__device__ float4 d_m[NN];      // layer2 v4 accumulator (reset in node3)
__device__ float  d_n[NN];      // layer2 scalar accumulator (reset in node3)
__device__ float  d_degx[NN];   // degree-1 (reset in node3)
__device__ float  d_dinv[NN];   // overwritten
__device__ double d_sum[4];     // reset in node2
__device__ double d_sumsq[4];   // reset in node2
__device__ float  d_acc[NG * 8];// reset in final

__device__ __forceinline__ void red4v(float4* p, float4 v) {
    asm volatile("red.global.add.v4.f32 [%0], {%1,%2,%3,%4};"
                 :: "l"(p), "f"(v.x), "f"(v.y), "f"(v.z), "f"(v.w) : "memory");
}
__device__ __forceinline__ void red1(float* p, float a) {
    asm volatile("red.global.add.f32 [%0], %1;" :: "l"(p), "f"(a) : "memory");
}

// Fused: degree accumulation (8 edges/thread) + BN0 statistics
__global__ void __launch_bounds__(256) k_pre(const float* __restrict__ x,
                                             const int* __restrict__ ei) {
    int t = blockIdx.x * blockDim.x + threadIdx.x;
    if (t < NE / 8) {
        const int4* dp = (const int4*)(ei + NE);
        int4 d0 = dp[2 * t];
        int4 d1 = dp[2 * t + 1];
        red1(&d_degx[d0.x], 1.0f);
        red1(&d_degx[d0.y], 1.0f);
        red1(&d_degx[d0.z], 1.0f);
        red1(&d_degx[d0.w], 1.0f);
        red1(&d_degx[d1.x], 1.0f);
        red1(&d_degx[d1.y], 1.0f);
        red1(&d_degx[d1.z], 1.0f);
        red1(&d_degx[d1.w], 1.0f);
    }
    if (blockIdx.x < 256) {
        int j0 = blockIdx.x * blockDim.x + threadIdx.x;
        int stride = 256 * blockDim.x;
        double s0 = 0, s1 = 0, s2 = 0, s3 = 0;
        double q0 = 0, q1 = 0, q2 = 0, q3 = 0;
        for (int j = j0; j < NN; j += stride) {
            float4 v = ((const float4*)x)[j];
            s0 += v.x; q0 += (double)v.x * v.x;
            s1 += v.y; q1 += (double)v.y * v.y;
            s2 += v.z; q2 += (double)v.z * v.z;
            s3 += v.w; q3 += (double)v.w * v.w;
        }
        #pragma unroll
        for (int o = 16; o > 0; o >>= 1) {
            s0 += __shfl_down_sync(0xffffffffu, s0, o);
            s1 += __shfl_down_sync(0xffffffffu, s1, o);
            s2 += __shfl_down_sync(0xffffffffu, s2, o);
            s3 += __shfl_down_sync(0xffffffffu, s3, o);
            q0 += __shfl_down_sync(0xffffffffu, q0, o);
            q1 += __shfl_down_sync(0xffffffffu, q1, o);
            q2 += __shfl_down_sync(0xffffffffu, q2, o);
            q3 += __shfl_down_sync(0xffffffffu, q3, o);
        }
        if ((threadIdx.x & 31) == 0) {
            atomicAdd(&d_sum[0], s0); atomicAdd(&d_sumsq[0], q0);
            atomicAdd(&d_sum[1], s1); atomicAdd(&d_sumsq[1], q1);
            atomicAdd(&d_sum[2], s2); atomicAdd(&d_sumsq[2], q2);
            atomicAdd(&d_sum[3], s3); atomicAdd(&d_sumsq[3], q3);
        }
    }
}

// BN0 normalize + dinv + y; BN constants computed per block (1 thread, bcast)
__global__ void k_node1(const float* __restrict__ x,
                        const float* __restrict__ g0,
                        const float* __restrict__ b0) {
    __shared__ float sbn[12];
    if (threadIdx.x == 0) {
        #pragma unroll
        for (int c = 0; c < 4; c++) {
            double m = d_sum[c] / (double)NN;
            double var = d_sumsq[c] / (double)NN - m * m;
            sbn[c] = (float)m;
            sbn[4 + c] = rsqrtf((float)var + EPS) * g0[c];
            sbn[8 + c] = b0[c];
        }
    }
    __syncthreads();
    int i = blockIdx.x * blockDim.x + threadIdx.x;
    if (i >= NN) return;
    float4 v = ((const float4*)x)[i];
    float4 o;
    o.x = (v.x - sbn[0]) * sbn[4] + sbn[8];
    o.y = (v.y - sbn[1]) * sbn[5] + sbn[9];
    o.z = (v.z - sbn[2]) * sbn[6] + sbn[10];
    o.w = (v.w - sbn[3]) * sbn[7] + sbn[11];
    d_xn[i] = o;
    float di = rsqrtf(d_degx[i] + 1.0f);
    d_dinv[i] = di;
    float4 y;
    y.x = o.x * di; y.y = o.y * di; y.z = o.z * di; y.w = o.w * di;
    d_y[i] = y;
}

// agg_raw[d] += y[s], 8 edges/thread
__global__ void __launch_bounds__(256) k_edge1(const int* __restrict__ ei) {
    int t = blockIdx.x * blockDim.x + threadIdx.x;
    if (t >= NE / 8) return;
    const int4* sp = (const int4*)ei;
    const int4* dp = (const int4*)(ei + NE);
    int4 s0 = sp[2 * t], s1 = sp[2 * t + 1];
    int4 d0 = dp[2 * t], d1 = dp[2 * t + 1];
    float4 y0 = d_y[s0.x];
    float4 y1 = d_y[s0.y];
    float4 y2 = d_y[s0.z];
    float4 y3 = d_y[s0.w];
    float4 y4 = d_y[s1.x];
    float4 y5 = d_y[s1.y];
    float4 y6 = d_y[s1.z];
    float4 y7 = d_y[s1.w];
    red4v(&d_a1[d0.x], y0);
    red4v(&d_a1[d0.y], y1);
    red4v(&d_a1[d0.z], y2);
    red4v(&d_a1[d0.w], y3);
    red4v(&d_a1[d1.x], y4);
    red4v(&d_a1[d1.y], y5);
    red4v(&d_a1[d1.z], y6);
    red4v(&d_a1[d1.w], y7);
}

// z = di^2*agg_raw + di^3*xn ; reset BN sums for next replay
__global__ void k_node2() {
    int i = blockIdx.x * blockDim.x + threadIdx.x;
    if (blockIdx.x == 0 && threadIdx.x < 4) {
        d_sum[threadIdx.x] = 0.0;
        d_sumsq[threadIdx.x] = 0.0;
    }
    if (i >= NN) return;
    float di = d_dinv[i];
    float di2 = di * di;
    float di3 = di2 * di;
    float4 a = d_a1[i];
    float4 xv = d_xn[i];
    float4 z;
    z.x = a.x * di2 + xv.x * di3;
    z.y = a.y * di2 + xv.y * di3;
    z.z = a.z * di2 + xv.z * di3;
    z.w = a.w * di2 + xv.w * di3;
    d_a1[i] = z;
}

// m[d] += z[s]; n[d] += dinv[s], 8 edges/thread
__global__ void __launch_bounds__(256) k_edge2(const int* __restrict__ ei) {
    int t = blockIdx.x * blockDim.x + threadIdx.x;
    if (t >= NE / 8) return;
    const int4* sp = (const int4*)ei;
    const int4* dp = (const int4*)(ei + NE);
    int4 s0 = sp[2 * t], s1 = sp[2 * t + 1];
    int4 d0 = dp[2 * t], d1 = dp[2 * t + 1];
    float4 z0 = d_a1[s0.x];
    float4 z1 = d_a1[s0.y];
    float4 z2 = d_a1[s0.z];
    float4 z3 = d_a1[s0.w];
    float4 z4 = d_a1[s1.x];
    float4 z5 = d_a1[s1.y];
    float4 z6 = d_a1[s1.z];
    float4 z7 = d_a1[s1.w];
    float n0 = d_dinv[s0.x];
    float n1 = d_dinv[s0.y];
    float n2 = d_dinv[s0.z];
    float n3 = d_dinv[s0.w];
    float n4 = d_dinv[s1.x];
    float n5 = d_dinv[s1.y];
    float n6 = d_dinv[s1.z];
    float n7 = d_dinv[s1.w];
    red4v(&d_m[d0.x], z0); red1(&d_n[d0.x], n0);
    red4v(&d_m[d0.y], z1); red1(&d_n[d0.y], n1);
    red4v(&d_m[d0.z], z2); red1(&d_n[d0.z], n2);
    red4v(&d_m[d0.w], z3); red1(&d_n[d0.w], n3);
    red4v(&d_m[d1.x], z4); red1(&d_n[d1.x], n4);
    red4v(&d_m[d1.y], z5); red1(&d_n[d1.y], n5);
    red4v(&d_m[d1.z], z6); red1(&d_n[d1.z], n6);
    red4v(&d_m[d1.w], z7); red1(&d_n[d1.w], n7);
}

// per-graph reduction; resets node accumulators
#define NCOPY 4
__global__ void k_node3(const int* __restrict__ batch) {
    __shared__ float sacc[NCOPY][NG * 6];
    for (int j = threadIdx.x; j < NCOPY * NG * 6; j += blockDim.x)
        ((float*)sacc)[j] = 0.f;
    __syncthreads();
    int w = (threadIdx.x >> 5) & (NCOPY - 1);
    int stride = gridDim.x * blockDim.x;
    const float4 z4 = make_float4(0.f, 0.f, 0.f, 0.f);
    for (int i = blockIdx.x * blockDim.x + threadIdx.x; i < NN; i += stride) {
        float di = d_dinv[i];
        float4 m = d_m[i];
        float4 z = d_a1[i];
        float n = d_n[i];
        int g = batch[i];
        d_m[i] = z4;
        d_a1[i] = z4;
        d_n[i] = 0.f;
        d_degx[i] = 0.f;
        float* p = &sacc[w][g * 6];
        atomicAdd(p + 0, di * (m.x + z.x));
        atomicAdd(p + 1, di * (m.y + z.y));
        atomicAdd(p + 2, di * (m.z + z.z));
        atomicAdd(p + 3, di * (m.w + z.w));
        atomicAdd(p + 4, di * (n + di));
        atomicAdd(p + 5, 1.0f);
    }
    __syncthreads();
    for (int j = threadIdx.x; j < NG * 6; j += blockDim.x) {
        float v = 0.f;
        #pragma unroll
        for (int k = 0; k < NCOPY; k++) v += sacc[k][j];
        int g = j / 6, c = j % 6;
        red1(&d_acc[g * 8 + c], v);
    }
}

// One block, 64 threads: W0/W1 apply, BN1, MLP; resets d_acc
__global__ void k_final(const float* __restrict__ W0, const float* __restrict__ b0,
                        const float* __restrict__ W1, const float* __restrict__ b1,
                        const float* __restrict__ bn1g, const float* __restrict__ bn1b,
                        const float* __restrict__ l0W, const float* __restrict__ l0b,
                        const float* __restrict__ l1W, const float* __restrict__ l1b,
                        const float* __restrict__ oW, const float* __restrict__ ob,
                        float* __restrict__ out) {
    __shared__ float sg[64][65];
    __shared__ float sW[64 * 64];
    int t = threadIdx.x;

    for (int j = t; j < 4096; j += 64) sW[j] = W1[j];

    float* acc = &d_acc[t * 8];
    float s4[4];
    #pragma unroll
    for (int c = 0; c < 4; c++) s4[c] = acc[c];
    float ss = acc[4];
    float ng = acc[5];
    #pragma unroll
    for (int c = 0; c < 8; c++) acc[c] = 0.f;

    float h[64];
    #pragma unroll
    for (int j = 0; j < 64; j++)
        h[j] = ss * b0[j] + s4[0] * W0[j] + s4[1] * W0[64 + j]
             + s4[2] * W0[128 + j] + s4[3] * W0[192 + j];
    __syncthreads();

    for (int j = 0; j < 64; j++) {
        float a = ng * b1[j];
        #pragma unroll
        for (int k = 0; k < 64; k++) a += h[k] * sW[k * 64 + j];
        sg[t][j] = a;
    }
    __syncthreads();

    {
        float m = 0.f;
        for (int G = 0; G < 64; G++) m += sg[G][t];
        m *= (1.0f / 64.0f);
        float v = 0.f;
        for (int G = 0; G < 64; G++) { float d = sg[G][t] - m; v += d * d; }
        v *= (1.0f / 64.0f);
        float r = rsqrtf(v + EPS) * bn1g[t];
        float bb = bn1b[t];
        for (int G = 0; G < 64; G++) sg[G][t] = (sg[G][t] - m) * r + bb;
    }
    __syncthreads();

    float h2[64];
    #pragma unroll
    for (int k = 0; k < 64; k++) h2[k] = sg[t][k];
    __syncthreads();
    for (int j = t; j < 4096; j += 64) sW[j] = l0W[j];
    __syncthreads();
    for (int j = 0; j < 64; j++) {
        float a = l0b[j];
        #pragma unroll
        for (int k = 0; k < 64; k++) a += h2[k] * sW[k * 64 + j];
        sg[t][j] = a;
    }
    __syncthreads();

    #pragma unroll
    for (int k = 0; k < 64; k++) h2[k] = sg[t][k];
    __syncthreads();
    for (int j = t; j < 4096; j += 64) sW[j] = l1W[j];
    __syncthreads();
    float o = ob[0];
    for (int j = 0; j < 64; j++) {
        float a = l1b[j];
        #pragma unroll
        for (int k = 0; k < 64; k++) a += h2[k] * sW[k * 64 + j];
        o += a * oW[j];
    }
    out[t] = o;
}

extern "C" void kernel_launch(void* const* d_in, const int* in_sizes, int n_in,
                              void* d_out, int out_size) {
    const float* x     = (const float*)d_in[0];
    const int*   ei    = (const int*)d_in[1];
    const int*   batch = (const int*)d_in[2];
    const float* bn0g = (const float*)d_in[3];
    const float* bn0b = (const float*)d_in[4];
    const float* W0   = (const float*)d_in[5];
    const float* b0   = (const float*)d_in[6];
    const float* W1   = (const float*)d_in[7];
    const float* b1   = (const float*)d_in[8];
    const float* bn1g = (const float*)d_in[9];
    const float* bn1b = (const float*)d_in[10];
    const float* l0W  = (const float*)d_in[11];
    const float* l0b  = (const float*)d_in[12];
    const float* l1W  = (const float*)d_in[13];
    const float* l1b  = (const float*)d_in[14];
    const float* oW   = (const float*)d_in[15];
    const float* ob   = (const float*)d_in[16];
    float* out = (float*)d_out;

    int et8 = NE / 8;  // 400K threads
    k_pre  <<<(et8 + 255) / 256, 256>>>(x, ei);
    k_node1<<<(NN + 255) / 256, 256>>>(x, bn0g, bn0b);
    k_edge1<<<(et8 + 255) / 256, 256>>>(ei);
    k_node2<<<(NN + 255) / 256, 256>>>();
    k_edge2<<<(et8 + 255) / 256, 256>>>(ei);
    k_node3<<<148, 256>>>(batch);
    k_final<<<1, 64>>>(W0, b0, W1, b1, bn1g, bn1b,
                       l0W, l0b, l1W, l1b, oW, ob, out);
}

// round 9
// speedup vs baseline: 1.7664x; 1.0315x over previous
#include <cuda_runtime.h>
#include <cuda_fp16.h>

#define NN 100000
#define NE 3200000
#define NG 64
#define EPS 1e-5f

// Scratch (__device__ globals; accumulators are zero at rest — each kernel
// that last reads one resets it for the next graph replay).
__device__ float4 d_xn[NN];     // overwritten each run
__device__ float4 d_y[NN];      // overwritten each run
__device__ float4 d_a1[NN];     // raw agg accumulator (reset in node2)
__device__ float4 d_zp[NN];     // packed {half2 z01, half2 z23, f32 dinv, pad} (overwritten)
__device__ float4 d_m[NN];      // layer2 v4 accumulator (reset in node3)
__device__ float  d_n[NN];      // layer2 scalar accumulator (reset in node3)
__device__ float  d_degx[NN];   // degree-1 (reset in node3)
__device__ float  d_dinv[NN];   // overwritten
__device__ double d_sum[4];     // reset in node2
__device__ double d_sumsq[4];   // reset in node2
__device__ float  d_acc[NG * 8];// reset in final

__device__ __forceinline__ void red4(float4* p, float a, float b, float c, float d) {
    asm volatile("red.global.add.v4.f32 [%0], {%1,%2,%3,%4};"
                 :: "l"(p), "f"(a), "f"(b), "f"(c), "f"(d) : "memory");
}
__device__ __forceinline__ void red4v(float4* p, float4 v) {
    asm volatile("red.global.add.v4.f32 [%0], {%1,%2,%3,%4};"
                 :: "l"(p), "f"(v.x), "f"(v.y), "f"(v.z), "f"(v.w) : "memory");
}
__device__ __forceinline__ void red1(float* p, float a) {
    asm volatile("red.global.add.f32 [%0], %1;" :: "l"(p), "f"(a) : "memory");
}

// Fused: degree accumulation (8 edges/thread) + BN0 statistics
__global__ void __launch_bounds__(256) k_pre(const float* __restrict__ x,
                                             const int* __restrict__ ei) {
    int t = blockIdx.x * blockDim.x + threadIdx.x;
    if (t < NE / 8) {
        const int4* dp = (const int4*)(ei + NE);
        int4 d0 = dp[2 * t];
        int4 d1 = dp[2 * t + 1];
        red1(&d_degx[d0.x], 1.0f);
        red1(&d_degx[d0.y], 1.0f);
        red1(&d_degx[d0.z], 1.0f);
        red1(&d_degx[d0.w], 1.0f);
        red1(&d_degx[d1.x], 1.0f);
        red1(&d_degx[d1.y], 1.0f);
        red1(&d_degx[d1.z], 1.0f);
        red1(&d_degx[d1.w], 1.0f);
    }
    if (blockIdx.x < 256) {
        int j0 = blockIdx.x * blockDim.x + threadIdx.x;
        int stride = 256 * blockDim.x;
        double s0 = 0, s1 = 0, s2 = 0, s3 = 0;
        double q0 = 0, q1 = 0, q2 = 0, q3 = 0;
        for (int j = j0; j < NN; j += stride) {
            float4 v = ((const float4*)x)[j];
            s0 += v.x; q0 += (double)v.x * v.x;
            s1 += v.y; q1 += (double)v.y * v.y;
            s2 += v.z; q2 += (double)v.z * v.z;
            s3 += v.w; q3 += (double)v.w * v.w;
        }
        #pragma unroll
        for (int o = 16; o > 0; o >>= 1) {
            s0 += __shfl_down_sync(0xffffffffu, s0, o);
            s1 += __shfl_down_sync(0xffffffffu, s1, o);
            s2 += __shfl_down_sync(0xffffffffu, s2, o);
            s3 += __shfl_down_sync(0xffffffffu, s3, o);
            q0 += __shfl_down_sync(0xffffffffu, q0, o);
            q1 += __shfl_down_sync(0xffffffffu, q1, o);
            q2 += __shfl_down_sync(0xffffffffu, q2, o);
            q3 += __shfl_down_sync(0xffffffffu, q3, o);
        }
        if ((threadIdx.x & 31) == 0) {
            atomicAdd(&d_sum[0], s0); atomicAdd(&d_sumsq[0], q0);
            atomicAdd(&d_sum[1], s1); atomicAdd(&d_sumsq[1], q1);
            atomicAdd(&d_sum[2], s2); atomicAdd(&d_sumsq[2], q2);
            atomicAdd(&d_sum[3], s3); atomicAdd(&d_sumsq[3], q3);
        }
    }
}

// BN0 normalize + dinv + y; BN constants computed per block (1 thread, bcast)
__global__ void k_node1(const float* __restrict__ x,
                        const float* __restrict__ g0,
                        const float* __restrict__ b0) {
    __shared__ float sbn[12];
    if (threadIdx.x == 0) {
        #pragma unroll
        for (int c = 0; c < 4; c++) {
            double m = d_sum[c] / (double)NN;
            double var = d_sumsq[c] / (double)NN - m * m;
            sbn[c] = (float)m;
            sbn[4 + c] = rsqrtf((float)var + EPS) * g0[c];
            sbn[8 + c] = b0[c];
        }
    }
    __syncthreads();
    int i = blockIdx.x * blockDim.x + threadIdx.x;
    if (i >= NN) return;
    float4 v = ((const float4*)x)[i];
    float4 o;
    o.x = (v.x - sbn[0]) * sbn[4] + sbn[8];
    o.y = (v.y - sbn[1]) * sbn[5] + sbn[9];
    o.z = (v.z - sbn[2]) * sbn[6] + sbn[10];
    o.w = (v.w - sbn[3]) * sbn[7] + sbn[11];
    d_xn[i] = o;
    float di = rsqrtf(d_degx[i] + 1.0f);
    d_dinv[i] = di;
    float4 y;
    y.x = o.x * di; y.y = o.y * di; y.z = o.z * di; y.w = o.w * di;
    d_y[i] = y;
}

// agg_raw[d] += y[s], 8 edges/thread
__global__ void __launch_bounds__(256) k_edge1(const int* __restrict__ ei) {
    int t = blockIdx.x * blockDim.x + threadIdx.x;
    if (t >= NE / 8) return;
    const int4* sp = (const int4*)ei;
    const int4* dp = (const int4*)(ei + NE);
    int4 s0 = sp[2 * t], s1 = sp[2 * t + 1];
    int4 d0 = dp[2 * t], d1 = dp[2 * t + 1];
    float4 y0 = d_y[s0.x];
    float4 y1 = d_y[s0.y];
    float4 y2 = d_y[s0.z];
    float4 y3 = d_y[s0.w];
    float4 y4 = d_y[s1.x];
    float4 y5 = d_y[s1.y];
    float4 y6 = d_y[s1.z];
    float4 y7 = d_y[s1.w];
    red4v(&d_a1[d0.x], y0);
    red4v(&d_a1[d0.y], y1);
    red4v(&d_a1[d0.z], y2);
    red4v(&d_a1[d0.w], y3);
    red4v(&d_a1[d1.x], y4);
    red4v(&d_a1[d1.y], y5);
    red4v(&d_a1[d1.z], y6);
    red4v(&d_a1[d1.w], y7);
}

// z = di^2*agg_raw + di^3*xn, packed to {half2,half2,dinv,0}; resets d_a1 and BN sums
__global__ void k_node2() {
    int i = blockIdx.x * blockDim.x + threadIdx.x;
    if (blockIdx.x == 0 && threadIdx.x < 4) {
        d_sum[threadIdx.x] = 0.0;
        d_sumsq[threadIdx.x] = 0.0;
    }
    if (i >= NN) return;
    float di = d_dinv[i];
    float di2 = di * di;
    float di3 = di2 * di;
    float4 a = d_a1[i];
    float4 xv = d_xn[i];
    float zx = a.x * di2 + xv.x * di3;
    float zy = a.y * di2 + xv.y * di3;
    float zz = a.z * di2 + xv.z * di3;
    float zw = a.w * di2 + xv.w * di3;
    d_a1[i] = make_float4(0.f, 0.f, 0.f, 0.f);  // reset accumulator for next replay
    half2 h01 = __floats2half2_rn(zx, zy);
    half2 h23 = __floats2half2_rn(zz, zw);
    float4 p;
    p.x = *reinterpret_cast<float*>(&h01);
    p.y = *reinterpret_cast<float*>(&h23);
    p.z = di;
    p.w = 0.f;
    d_zp[i] = p;
}

// m[d] += z[s]; n[d] += dinv[s] — ONE packed gather per edge, 8 edges/thread
__global__ void __launch_bounds__(256) k_edge2(const int* __restrict__ ei) {
    int t = blockIdx.x * blockDim.x + threadIdx.x;
    if (t >= NE / 8) return;
    const int4* sp = (const int4*)ei;
    const int4* dp = (const int4*)(ei + NE);
    int4 s0 = sp[2 * t], s1 = sp[2 * t + 1];
    int4 d0 = dp[2 * t], d1 = dp[2 * t + 1];
    float4 p0 = d_zp[s0.x];
    float4 p1 = d_zp[s0.y];
    float4 p2 = d_zp[s0.z];
    float4 p3 = d_zp[s0.w];
    float4 p4 = d_zp[s1.x];
    float4 p5 = d_zp[s1.y];
    float4 p6 = d_zp[s1.z];
    float4 p7 = d_zp[s1.w];
    #define E2_ONE(p, dd) do {                                              \
        float2 _z01 = __half22float2(*reinterpret_cast<half2*>(&(p).x));    \
        float2 _z23 = __half22float2(*reinterpret_cast<half2*>(&(p).y));    \
        red4(&d_m[dd], _z01.x, _z01.y, _z23.x, _z23.y);                     \
        red1(&d_n[dd], (p).z);                                              \
    } while (0)
    E2_ONE(p0, d0.x);
    E2_ONE(p1, d0.y);
    E2_ONE(p2, d0.z);
    E2_ONE(p3, d0.w);
    E2_ONE(p4, d1.x);
    E2_ONE(p5, d1.y);
    E2_ONE(p6, d1.z);
    E2_ONE(p7, d1.w);
    #undef E2_ONE
}

// per-graph reduction; resets node accumulators
#define NCOPY 4
__global__ void k_node3(const int* __restrict__ batch) {
    __shared__ float sacc[NCOPY][NG * 6];
    for (int j = threadIdx.x; j < NCOPY * NG * 6; j += blockDim.x)
        ((float*)sacc)[j] = 0.f;
    __syncthreads();
    int w = (threadIdx.x >> 5) & (NCOPY - 1);
    int stride = gridDim.x * blockDim.x;
    const float4 z4 = make_float4(0.f, 0.f, 0.f, 0.f);
    for (int i = blockIdx.x * blockDim.x + threadIdx.x; i < NN; i += stride) {
        float4 p = d_zp[i];
        float4 m = d_m[i];
        float n = d_n[i];
        int g = batch[i];
        d_m[i] = z4;
        d_n[i] = 0.f;
        d_degx[i] = 0.f;
        float di = p.z;
        float2 z01 = __half22float2(*reinterpret_cast<half2*>(&p.x));
        float2 z23 = __half22float2(*reinterpret_cast<half2*>(&p.y));
        float* pp = &sacc[w][g * 6];
        atomicAdd(pp + 0, di * (m.x + z01.x));
        atomicAdd(pp + 1, di * (m.y + z01.y));
        atomicAdd(pp + 2, di * (m.z + z23.x));
        atomicAdd(pp + 3, di * (m.w + z23.y));
        atomicAdd(pp + 4, di * (n + di));
        atomicAdd(pp + 5, 1.0f);
    }
    __syncthreads();
    for (int j = threadIdx.x; j < NG * 6; j += blockDim.x) {
        float v = 0.f;
        #pragma unroll
        for (int k = 0; k < NCOPY; k++) v += sacc[k][j];
        int g = j / 6, c = j % 6;
        red1(&d_acc[g * 8 + c], v);
    }
}

// One block, 64 threads: W0/W1 apply, BN1, MLP; resets d_acc
__global__ void k_final(const float* __restrict__ W0, const float* __restrict__ b0,
                        const float* __restrict__ W1, const float* __restrict__ b1,
                        const float* __restrict__ bn1g, const float* __restrict__ bn1b,
                        const float* __restrict__ l0W, const float* __restrict__ l0b,
                        const float* __restrict__ l1W, const float* __restrict__ l1b,
                        const float* __restrict__ oW, const float* __restrict__ ob,
                        float* __restrict__ out) {
    __shared__ float sg[64][65];
    __shared__ float sW[64 * 64];
    int t = threadIdx.x;

    for (int j = t; j < 4096; j += 64) sW[j] = W1[j];

    float* acc = &d_acc[t * 8];
    float s4[4];
    #pragma unroll
    for (int c = 0; c < 4; c++) s4[c] = acc[c];
    float ss = acc[4];
    float ng = acc[5];
    #pragma unroll
    for (int c = 0; c < 8; c++) acc[c] = 0.f;

    float h[64];
    #pragma unroll
    for (int j = 0; j < 64; j++)
        h[j] = ss * b0[j] + s4[0] * W0[j] + s4[1] * W0[64 + j]
             + s4[2] * W0[128 + j] + s4[3] * W0[192 + j];
    __syncthreads();

    for (int j = 0; j < 64; j++) {
        float a = ng * b1[j];
        #pragma unroll
        for (int k = 0; k < 64; k++) a += h[k] * sW[k * 64 + j];
        sg[t][j] = a;
    }
    __syncthreads();

    {
        float m = 0.f;
        for (int G = 0; G < 64; G++) m += sg[G][t];
        m *= (1.0f / 64.0f);
        float v = 0.f;
        for (int G = 0; G < 64; G++) { float d = sg[G][t] - m; v += d * d; }
        v *= (1.0f / 64.0f);
        float r = rsqrtf(v + EPS) * bn1g[t];
        float bb = bn1b[t];
        for (int G = 0; G < 64; G++) sg[G][t] = (sg[G][t] - m) * r + bb;
    }
    __syncthreads();

    float h2[64];
    #pragma unroll
    for (int k = 0; k < 64; k++) h2[k] = sg[t][k];
    __syncthreads();
    for (int j = t; j < 4096; j += 64) sW[j] = l0W[j];
    __syncthreads();
    for (int j = 0; j < 64; j++) {
        float a = l0b[j];
        #pragma unroll
        for (int k = 0; k < 64; k++) a += h2[k] * sW[k * 64 + j];
        sg[t][j] = a;
    }
    __syncthreads();

    #pragma unroll
    for (int k = 0; k < 64; k++) h2[k] = sg[t][k];
    __syncthreads();
    for (int j = t; j < 4096; j += 64) sW[j] = l1W[j];
    __syncthreads();
    float o = ob[0];
    for (int j = 0; j < 64; j++) {
        float a = l1b[j];
        #pragma unroll
        for (int k = 0; k < 64; k++) a += h2[k] * sW[k * 64 + j];
        o += a * oW[j];
    }
    out[t] = o;
}

extern "C" void kernel_launch(void* const* d_in, const int* in_sizes, int n_in,
                              void* d_out, int out_size) {
    const float* x     = (const float*)d_in[0];
    const int*   ei    = (const int*)d_in[1];
    const int*   batch = (const int*)d_in[2];
    const float* bn0g = (const float*)d_in[3];
    const float* bn0b = (const float*)d_in[4];
    const float* W0   = (const float*)d_in[5];
    const float* b0   = (const float*)d_in[6];
    const float* W1   = (const float*)d_in[7];
    const float* b1   = (const float*)d_in[8];
    const float* bn1g = (const float*)d_in[9];
    const float* bn1b = (const float*)d_in[10];
    const float* l0W  = (const float*)d_in[11];
    const float* l0b  = (const float*)d_in[12];
    const float* l1W  = (const float*)d_in[13];
    const float* l1b  = (const float*)d_in[14];
    const float* oW   = (const float*)d_in[15];
    const float* ob   = (const float*)d_in[16];
    float* out = (float*)d_out;

    int et8 = NE / 8;  // 400K threads
    k_pre  <<<(et8 + 255) / 256, 256>>>(x, ei);
    k_node1<<<(NN + 255) / 256, 256>>>(x, bn0g, bn0b);
    k_edge1<<<(et8 + 255) / 256, 256>>>(ei);
    k_node2<<<(NN + 255) / 256, 256>>>();
    k_edge2<<<(et8 + 255) / 256, 256>>>(ei);
    k_node3<<<148, 256>>>(batch);
    k_final<<<1, 64>>>(W0, b0, W1, b1, bn1g, bn1b,
                       l0W, l0b, l1W, l1b, oW, ob, out);
}

// round 10
// speedup vs baseline: 2.1528x; 1.2187x over previous
#include <cuda_runtime.h>
#include <cuda_fp16.h>

#define NN 100000
#define NE 3200000
#define NG 64
#define EPS 1e-5f

// Scratch (__device__ globals; accumulators are zero at rest — each kernel
// that last reads one resets it for the next graph replay).
__device__ float4 d_xn[NN];     // overwritten each run
__device__ float4 d_y[NN];      // overwritten each run
__device__ float4 d_a1[NN];     // raw agg accumulator (reset in node2)
__device__ float4 d_zp[NN];     // packed {half2 z01, half2 z23, f32 dinv, pad}
__device__ float4 d_m[NN];      // layer2 v4 accumulator (reset in node3)
__device__ float  d_n[NN];      // layer2 scalar accumulator (reset in node3)
__device__ float  d_degx[NN];   // degree-1 (reset in node3)
__device__ float  d_dinv[NN];   // overwritten
__device__ double d_sum[4];     // reset in node2
__device__ double d_sumsq[4];   // reset in node2
__device__ int    d_needn;      // 1 iff conv1 bias b0 has any nonzero (overwritten in node1)
__device__ float  d_acc[NG * 8];// reset in final

__device__ __forceinline__ void red4(float4* p, float a, float b, float c, float d) {
    asm volatile("red.global.add.v4.f32 [%0], {%1,%2,%3,%4};"
                 :: "l"(p), "f"(a), "f"(b), "f"(c), "f"(d) : "memory");
}
__device__ __forceinline__ void red4v(float4* p, float4 v) {
    asm volatile("red.global.add.v4.f32 [%0], {%1,%2,%3,%4};"
                 :: "l"(p), "f"(v.x), "f"(v.y), "f"(v.z), "f"(v.w) : "memory");
}
__device__ __forceinline__ void red1(float* p, float a) {
    asm volatile("red.global.add.f32 [%0], %1;" :: "l"(p), "f"(a) : "memory");
}

// Fused: degree accumulation (8 edges/thread) + BN0 statistics
__global__ void __launch_bounds__(256) k_pre(const float* __restrict__ x,
                                             const int* __restrict__ ei) {
    int t = blockIdx.x * blockDim.x + threadIdx.x;
    if (t < NE / 8) {
        const int4* dp = (const int4*)(ei + NE);
        int4 d0 = dp[2 * t];
        int4 d1 = dp[2 * t + 1];
        red1(&d_degx[d0.x], 1.0f);
        red1(&d_degx[d0.y], 1.0f);
        red1(&d_degx[d0.z], 1.0f);
        red1(&d_degx[d0.w], 1.0f);
        red1(&d_degx[d1.x], 1.0f);
        red1(&d_degx[d1.y], 1.0f);
        red1(&d_degx[d1.z], 1.0f);
        red1(&d_degx[d1.w], 1.0f);
    }
    if (blockIdx.x < 256) {
        int j0 = blockIdx.x * blockDim.x + threadIdx.x;
        int stride = 256 * blockDim.x;
        double s0 = 0, s1 = 0, s2 = 0, s3 = 0;
        double q0 = 0, q1 = 0, q2 = 0, q3 = 0;
        for (int j = j0; j < NN; j += stride) {
            float4 v = ((const float4*)x)[j];
            s0 += v.x; q0 += (double)v.x * v.x;
            s1 += v.y; q1 += (double)v.y * v.y;
            s2 += v.z; q2 += (double)v.z * v.z;
            s3 += v.w; q3 += (double)v.w * v.w;
        }
        #pragma unroll
        for (int o = 16; o > 0; o >>= 1) {
            s0 += __shfl_down_sync(0xffffffffu, s0, o);
            s1 += __shfl_down_sync(0xffffffffu, s1, o);
            s2 += __shfl_down_sync(0xffffffffu, s2, o);
            s3 += __shfl_down_sync(0xffffffffu, s3, o);
            q0 += __shfl_down_sync(0xffffffffu, q0, o);
            q1 += __shfl_down_sync(0xffffffffu, q1, o);
            q2 += __shfl_down_sync(0xffffffffu, q2, o);
            q3 += __shfl_down_sync(0xffffffffu, q3, o);
        }
        if ((threadIdx.x & 31) == 0) {
            atomicAdd(&d_sum[0], s0); atomicAdd(&d_sumsq[0], q0);
            atomicAdd(&d_sum[1], s1); atomicAdd(&d_sumsq[1], q1);
            atomicAdd(&d_sum[2], s2); atomicAdd(&d_sumsq[2], q2);
            atomicAdd(&d_sum[3], s3); atomicAdd(&d_sumsq[3], q3);
        }
    }
}

// BN0 normalize + dinv + y; also computes d_needn from conv1 bias b0c
__global__ void k_node1(const float* __restrict__ x,
                        const float* __restrict__ g0,
                        const float* __restrict__ b0,
                        const float* __restrict__ b0c) {
    __shared__ float sbn[12];
    if (threadIdx.x == 0) {
        #pragma unroll
        for (int c = 0; c < 4; c++) {
            double m = d_sum[c] / (double)NN;
            double var = d_sumsq[c] / (double)NN - m * m;
            sbn[c] = (float)m;
            sbn[4 + c] = rsqrtf((float)var + EPS) * g0[c];
            sbn[8 + c] = b0[c];
        }
        if (blockIdx.x == 0) {
            float mx = 0.f;
            for (int j = 0; j < 64; j++) mx = fmaxf(mx, fabsf(b0c[j]));
            d_needn = (mx > 0.f) ? 1 : 0;
        }
    }
    __syncthreads();
    int i = blockIdx.x * blockDim.x + threadIdx.x;
    if (i >= NN) return;
    float4 v = ((const float4*)x)[i];
    float4 o;
    o.x = (v.x - sbn[0]) * sbn[4] + sbn[8];
    o.y = (v.y - sbn[1]) * sbn[5] + sbn[9];
    o.z = (v.z - sbn[2]) * sbn[6] + sbn[10];
    o.w = (v.w - sbn[3]) * sbn[7] + sbn[11];
    d_xn[i] = o;
    float di = rsqrtf(d_degx[i] + 1.0f);
    d_dinv[i] = di;
    float4 y;
    y.x = o.x * di; y.y = o.y * di; y.z = o.z * di; y.w = o.w * di;
    d_y[i] = y;
}

// agg_raw[d] += y[s], 8 edges/thread
__global__ void __launch_bounds__(256) k_edge1(const int* __restrict__ ei) {
    int t = blockIdx.x * blockDim.x + threadIdx.x;
    if (t >= NE / 8) return;
    const int4* sp = (const int4*)ei;
    const int4* dp = (const int4*)(ei + NE);
    int4 s0 = sp[2 * t], s1 = sp[2 * t + 1];
    int4 d0 = dp[2 * t], d1 = dp[2 * t + 1];
    float4 y0 = d_y[s0.x];
    float4 y1 = d_y[s0.y];
    float4 y2 = d_y[s0.z];
    float4 y3 = d_y[s0.w];
    float4 y4 = d_y[s1.x];
    float4 y5 = d_y[s1.y];
    float4 y6 = d_y[s1.z];
    float4 y7 = d_y[s1.w];
    red4v(&d_a1[d0.x], y0);
    red4v(&d_a1[d0.y], y1);
    red4v(&d_a1[d0.z], y2);
    red4v(&d_a1[d0.w], y3);
    red4v(&d_a1[d1.x], y4);
    red4v(&d_a1[d1.y], y5);
    red4v(&d_a1[d1.z], y6);
    red4v(&d_a1[d1.w], y7);
}

// z = di^2*agg_raw + di^3*xn, packed to {half2,half2,dinv,0}; resets d_a1 and BN sums
__global__ void k_node2() {
    int i = blockIdx.x * blockDim.x + threadIdx.x;
    if (blockIdx.x == 0 && threadIdx.x < 4) {
        d_sum[threadIdx.x] = 0.0;
        d_sumsq[threadIdx.x] = 0.0;
    }
    if (i >= NN) return;
    float di = d_dinv[i];
    float di2 = di * di;
    float di3 = di2 * di;
    float4 a = d_a1[i];
    float4 xv = d_xn[i];
    float zx = a.x * di2 + xv.x * di3;
    float zy = a.y * di2 + xv.y * di3;
    float zz = a.z * di2 + xv.z * di3;
    float zw = a.w * di2 + xv.w * di3;
    d_a1[i] = make_float4(0.f, 0.f, 0.f, 0.f);  // reset accumulator for next replay
    half2 h01 = __floats2half2_rn(zx, zy);
    half2 h23 = __floats2half2_rn(zz, zw);
    float4 p;
    p.x = *reinterpret_cast<float*>(&h01);
    p.y = *reinterpret_cast<float*>(&h23);
    p.z = di;
    p.w = 0.f;
    d_zp[i] = p;
}

// m[d] += z[s]; n[d] += dinv[s] only when conv1 bias is nonzero (d_needn)
__global__ void __launch_bounds__(256) k_edge2(const int* __restrict__ ei) {
    int t = blockIdx.x * blockDim.x + threadIdx.x;
    if (t >= NE / 8) return;
    int needn = d_needn;
    const int4* sp = (const int4*)ei;
    const int4* dp = (const int4*)(ei + NE);
    int4 s0 = sp[2 * t], s1 = sp[2 * t + 1];
    int4 d0 = dp[2 * t], d1 = dp[2 * t + 1];
    float4 p0 = d_zp[s0.x];
    float4 p1 = d_zp[s0.y];
    float4 p2 = d_zp[s0.z];
    float4 p3 = d_zp[s0.w];
    float4 p4 = d_zp[s1.x];
    float4 p5 = d_zp[s1.y];
    float4 p6 = d_zp[s1.z];
    float4 p7 = d_zp[s1.w];
    #define E2_M(p, dd) do {                                                \
        float2 _z01 = __half22float2(*reinterpret_cast<half2*>(&(p).x));    \
        float2 _z23 = __half22float2(*reinterpret_cast<half2*>(&(p).y));    \
        red4(&d_m[dd], _z01.x, _z01.y, _z23.x, _z23.y);                     \
    } while (0)
    E2_M(p0, d0.x);
    E2_M(p1, d0.y);
    E2_M(p2, d0.z);
    E2_M(p3, d0.w);
    E2_M(p4, d1.x);
    E2_M(p5, d1.y);
    E2_M(p6, d1.z);
    E2_M(p7, d1.w);
    #undef E2_M
    if (needn) {
        red1(&d_n[d0.x], p0.z);
        red1(&d_n[d0.y], p1.z);
        red1(&d_n[d0.z], p2.z);
        red1(&d_n[d0.w], p3.z);
        red1(&d_n[d1.x], p4.z);
        red1(&d_n[d1.y], p5.z);
        red1(&d_n[d1.z], p6.z);
        red1(&d_n[d1.w], p7.z);
    }
}

// per-graph reduction; resets node accumulators
#define NCOPY 8
__global__ void k_node3(const int* __restrict__ batch) {
    __shared__ float sacc[NCOPY][NG * 6];
    for (int j = threadIdx.x; j < NCOPY * NG * 6; j += blockDim.x)
        ((float*)sacc)[j] = 0.f;
    __syncthreads();
    int w = (threadIdx.x >> 5) & (NCOPY - 1);
    int stride = gridDim.x * blockDim.x;
    const float4 z4 = make_float4(0.f, 0.f, 0.f, 0.f);
    for (int i = blockIdx.x * blockDim.x + threadIdx.x; i < NN; i += stride) {
        float4 p = d_zp[i];
        float4 m = d_m[i];
        float n = d_n[i];
        int g = batch[i];
        d_m[i] = z4;
        d_n[i] = 0.f;
        d_degx[i] = 0.f;
        float di = p.z;
        float2 z01 = __half22float2(*reinterpret_cast<half2*>(&p.x));
        float2 z23 = __half22float2(*reinterpret_cast<half2*>(&p.y));
        float* pp = &sacc[w][g * 6];
        atomicAdd(pp + 0, di * (m.x + z01.x));
        atomicAdd(pp + 1, di * (m.y + z01.y));
        atomicAdd(pp + 2, di * (m.z + z23.x));
        atomicAdd(pp + 3, di * (m.w + z23.y));
        atomicAdd(pp + 4, di * (n + di));
        atomicAdd(pp + 5, 1.0f);
    }
    __syncthreads();
    for (int j = threadIdx.x; j < NG * 6; j += blockDim.x) {
        float v = 0.f;
        #pragma unroll
        for (int k = 0; k < NCOPY; k++) v += sacc[k][j];
        int g = j / 6, c = j % 6;
        red1(&d_acc[g * 8 + c], v);
    }
}

// One block, 64 threads: W0/W1 apply, BN1, MLP; resets d_acc
__global__ void k_final(const float* __restrict__ W0, const float* __restrict__ b0,
                        const float* __restrict__ W1, const float* __restrict__ b1,
                        const float* __restrict__ bn1g, const float* __restrict__ bn1b,
                        const float* __restrict__ l0W, const float* __restrict__ l0b,
                        const float* __restrict__ l1W, const float* __restrict__ l1b,
                        const float* __restrict__ oW, const float* __restrict__ ob,
                        float* __restrict__ out) {
    __shared__ float sg[64][65];
    __shared__ float sW[64 * 64];
    int t = threadIdx.x;

    for (int j = t; j < 4096; j += 64) sW[j] = W1[j];

    float* acc = &d_acc[t * 8];
    float s4[4];
    #pragma unroll
    for (int c = 0; c < 4; c++) s4[c] = acc[c];
    float ss = acc[4];
    float ng = acc[5];
    #pragma unroll
    for (int c = 0; c < 8; c++) acc[c] = 0.f;

    float h[64];
    #pragma unroll
    for (int j = 0; j < 64; j++)
        h[j] = ss * b0[j] + s4[0] * W0[j] + s4[1] * W0[64 + j]
             + s4[2] * W0[128 + j] + s4[3] * W0[192 + j];
    __syncthreads();

    for (int j = 0; j < 64; j++) {
        float a = ng * b1[j];
        #pragma unroll
        for (int k = 0; k < 64; k++) a += h[k] * sW[k * 64 + j];
        sg[t][j] = a;
    }
    __syncthreads();

    {
        float m = 0.f;
        for (int G = 0; G < 64; G++) m += sg[G][t];
        m *= (1.0f / 64.0f);
        float v = 0.f;
        for (int G = 0; G < 64; G++) { float d = sg[G][t] - m; v += d * d; }
        v *= (1.0f / 64.0f);
        float r = rsqrtf(v + EPS) * bn1g[t];
        float bb = bn1b[t];
        for (int G = 0; G < 64; G++) sg[G][t] = (sg[G][t] - m) * r + bb;
    }
    __syncthreads();

    float h2[64];
    #pragma unroll
    for (int k = 0; k < 64; k++) h2[k] = sg[t][k];
    __syncthreads();
    for (int j = t; j < 4096; j += 64) sW[j] = l0W[j];
    __syncthreads();
    for (int j = 0; j < 64; j++) {
        float a = l0b[j];
        #pragma unroll
        for (int k = 0; k < 64; k++) a += h2[k] * sW[k * 64 + j];
        sg[t][j] = a;
    }
    __syncthreads();

    #pragma unroll
    for (int k = 0; k < 64; k++) h2[k] = sg[t][k];
    __syncthreads();
    for (int j = t; j < 4096; j += 64) sW[j] = l1W[j];
    __syncthreads();
    float o = ob[0];
    for (int j = 0; j < 64; j++) {
        float a = l1b[j];
        #pragma unroll
        for (int k = 0; k < 64; k++) a += h2[k] * sW[k * 64 + j];
        o += a * oW[j];
    }
    out[t] = o;
}

extern "C" void kernel_launch(void* const* d_in, const int* in_sizes, int n_in,
                              void* d_out, int out_size) {
    const float* x     = (const float*)d_in[0];
    const int*   ei    = (const int*)d_in[1];
    const int*   batch = (const int*)d_in[2];
    const float* bn0g = (const float*)d_in[3];
    const float* bn0b = (const float*)d_in[4];
    const float* W0   = (const float*)d_in[5];
    const float* b0   = (const float*)d_in[6];
    const float* W1   = (const float*)d_in[7];
    const float* b1   = (const float*)d_in[8];
    const float* bn1g = (const float*)d_in[9];
    const float* bn1b = (const float*)d_in[10];
    const float* l0W  = (const float*)d_in[11];
    const float* l0b  = (const float*)d_in[12];
    const float* l1W  = (const float*)d_in[13];
    const float* l1b  = (const float*)d_in[14];
    const float* oW   = (const float*)d_in[15];
    const float* ob   = (const float*)d_in[16];
    float* out = (float*)d_out;

    int et8 = NE / 8;  // 400K threads
    k_pre  <<<(et8 + 255) / 256, 256>>>(x, ei);
    k_node1<<<(NN + 255) / 256, 256>>>(x, bn0g, bn0b, b0);
    k_edge1<<<(et8 + 255) / 256, 256>>>(ei);
    k_node2<<<(NN + 255) / 256, 256>>>();
    k_edge2<<<(et8 + 255) / 256, 256>>>(ei);
    k_node3<<<148, 256>>>(batch);
    k_final<<<1, 64>>>(W0, b0, W1, b1, bn1g, bn1b,
                       l0W, l0b, l1W, l1b, oW, ob, out);
}

// round 11
// speedup vs baseline: 2.1932x; 1.0188x over previous
#include <cuda_runtime.h>
#include <cuda_fp16.h>

#define NN 100000
#define NE 3200000
#define NG 64
#define EPS 1e-5f

#define GDC_WAIT()   asm volatile("griddepcontrol.wait;" ::: "memory")
#define GDC_LAUNCH() asm volatile("griddepcontrol.launch_dependents;" ::: "memory")

// Scratch (__device__ globals; accumulators are zero at rest — each kernel
// that last reads one resets it for the next graph replay).
__device__ float4 d_xn[NN];
__device__ float4 d_y[NN];
__device__ float4 d_a1[NN];     // raw agg accumulator (reset in node2)
__device__ float4 d_zp[NN];     // packed {half2 z01, half2 z23, f32 dinv, pad}
__device__ float4 d_m[NN];      // layer2 v4 accumulator (reset in node3)
__device__ float  d_n[NN];      // layer2 scalar accumulator (reset in node3)
__device__ float  d_degx[NN];   // degree-1 (reset in node3)
__device__ float  d_dinv[NN];
__device__ double d_sum[4];     // reset in node2
__device__ double d_sumsq[4];   // reset in node2
__device__ int    d_needn;      // 1 iff conv1 bias b0 nonzero
__device__ float  d_acc[NG * 8];// reset in final

__device__ __forceinline__ void red4(float4* p, float a, float b, float c, float d) {
    asm volatile("red.global.add.v4.f32 [%0], {%1,%2,%3,%4};"
                 :: "l"(p), "f"(a), "f"(b), "f"(c), "f"(d) : "memory");
}
__device__ __forceinline__ void red4v(float4* p, float4 v) {
    asm volatile("red.global.add.v4.f32 [%0], {%1,%2,%3,%4};"
                 :: "l"(p), "f"(v.x), "f"(v.y), "f"(v.z), "f"(v.w) : "memory");
}
__device__ __forceinline__ void red1(float* p, float a) {
    asm volatile("red.global.add.f32 [%0], %1;" :: "l"(p), "f"(a) : "memory");
}

// Fused: degree accumulation (8 edges/thread) + BN0 statistics
__global__ void __launch_bounds__(256) k_pre(const float* __restrict__ x,
                                             const int* __restrict__ ei) {
    int t = blockIdx.x * blockDim.x + threadIdx.x;
    if (t < NE / 8) {
        const int4* dp = (const int4*)(ei + NE);
        int4 d0 = dp[2 * t];
        int4 d1 = dp[2 * t + 1];
        red1(&d_degx[d0.x], 1.0f);
        red1(&d_degx[d0.y], 1.0f);
        red1(&d_degx[d0.z], 1.0f);
        red1(&d_degx[d0.w], 1.0f);
        red1(&d_degx[d1.x], 1.0f);
        red1(&d_degx[d1.y], 1.0f);
        red1(&d_degx[d1.z], 1.0f);
        red1(&d_degx[d1.w], 1.0f);
    }
    if (blockIdx.x < 256) {
        int j0 = blockIdx.x * blockDim.x + threadIdx.x;
        int stride = 256 * blockDim.x;
        double s0 = 0, s1 = 0, s2 = 0, s3 = 0;
        double q0 = 0, q1 = 0, q2 = 0, q3 = 0;
        for (int j = j0; j < NN; j += stride) {
            float4 v = ((const float4*)x)[j];
            s0 += v.x; q0 += (double)v.x * v.x;
            s1 += v.y; q1 += (double)v.y * v.y;
            s2 += v.z; q2 += (double)v.z * v.z;
            s3 += v.w; q3 += (double)v.w * v.w;
        }
        #pragma unroll
        for (int o = 16; o > 0; o >>= 1) {
            s0 += __shfl_down_sync(0xffffffffu, s0, o);
            s1 += __shfl_down_sync(0xffffffffu, s1, o);
            s2 += __shfl_down_sync(0xffffffffu, s2, o);
            s3 += __shfl_down_sync(0xffffffffu, s3, o);
            q0 += __shfl_down_sync(0xffffffffu, q0, o);
            q1 += __shfl_down_sync(0xffffffffu, q1, o);
            q2 += __shfl_down_sync(0xffffffffu, q2, o);
            q3 += __shfl_down_sync(0xffffffffu, q3, o);
        }
        if ((threadIdx.x & 31) == 0) {
            atomicAdd(&d_sum[0], s0); atomicAdd(&d_sumsq[0], q0);
            atomicAdd(&d_sum[1], s1); atomicAdd(&d_sumsq[1], q1);
            atomicAdd(&d_sum[2], s2); atomicAdd(&d_sumsq[2], q2);
            atomicAdd(&d_sum[3], s3); atomicAdd(&d_sumsq[3], q3);
        }
    }
    GDC_LAUNCH();
}

// BN0 normalize + dinv + y; prelude: x load (input, independent of k_pre)
__global__ void __launch_bounds__(256) k_node1(const float* __restrict__ x,
                                               const float* __restrict__ g0,
                                               const float* __restrict__ b0,
                                               const float* __restrict__ b0c) {
    __shared__ float sbn[12];
    int i = blockIdx.x * blockDim.x + threadIdx.x;
    float4 v = make_float4(0.f, 0.f, 0.f, 0.f);
    if (i < NN) v = ((const float4*)x)[i];   // prelude load
    GDC_WAIT();
    if (threadIdx.x == 0) {
        #pragma unroll
        for (int c = 0; c < 4; c++) {
            double m = d_sum[c] / (double)NN;
            double var = d_sumsq[c] / (double)NN - m * m;
            sbn[c] = (float)m;
            sbn[4 + c] = rsqrtf((float)var + EPS) * g0[c];
            sbn[8 + c] = b0[c];
        }
        if (blockIdx.x == 0) {
            float mx = 0.f;
            for (int j = 0; j < 64; j++) mx = fmaxf(mx, fabsf(b0c[j]));
            d_needn = (mx > 0.f) ? 1 : 0;
        }
    }
    __syncthreads();
    if (i < NN) {
        float4 o;
        o.x = (v.x - sbn[0]) * sbn[4] + sbn[8];
        o.y = (v.y - sbn[1]) * sbn[5] + sbn[9];
        o.z = (v.z - sbn[2]) * sbn[6] + sbn[10];
        o.w = (v.w - sbn[3]) * sbn[7] + sbn[11];
        d_xn[i] = o;
        float di = rsqrtf(d_degx[i] + 1.0f);
        d_dinv[i] = di;
        float4 y;
        y.x = o.x * di; y.y = o.y * di; y.z = o.z * di; y.w = o.w * di;
        d_y[i] = y;
    }
    GDC_LAUNCH();
}

// agg_raw[d] += y[s], 8 edges/thread; prelude: index loads
__global__ void __launch_bounds__(256) k_edge1(const int* __restrict__ ei) {
    int t = blockIdx.x * blockDim.x + threadIdx.x;
    bool act = (t < NE / 8);
    int tt = act ? t : 0;
    const int4* sp = (const int4*)ei;
    const int4* dp = (const int4*)(ei + NE);
    int4 s0 = sp[2 * tt], s1 = sp[2 * tt + 1];   // prelude
    int4 d0 = dp[2 * tt], d1 = dp[2 * tt + 1];   // prelude
    GDC_WAIT();
    if (act) {
        float4 y0 = d_y[s0.x];
        float4 y1 = d_y[s0.y];
        float4 y2 = d_y[s0.z];
        float4 y3 = d_y[s0.w];
        float4 y4 = d_y[s1.x];
        float4 y5 = d_y[s1.y];
        float4 y6 = d_y[s1.z];
        float4 y7 = d_y[s1.w];
        red4v(&d_a1[d0.x], y0);
        red4v(&d_a1[d0.y], y1);
        red4v(&d_a1[d0.z], y2);
        red4v(&d_a1[d0.w], y3);
        red4v(&d_a1[d1.x], y4);
        red4v(&d_a1[d1.y], y5);
        red4v(&d_a1[d1.z], y6);
        red4v(&d_a1[d1.w], y7);
    }
    GDC_LAUNCH();
}

// z = di^2*agg_raw + di^3*xn, packed; 2 nodes/thread; resets d_a1 and BN sums
__global__ void __launch_bounds__(256) k_node2() {
    int t = blockIdx.x * blockDim.x + threadIdx.x;
    int i0 = 2 * t, i1 = 2 * t + 1;
    bool a0 = (i0 < NN), b1 = (i1 < NN);
    // prelude: xn/dinv were written by node1 (two kernels back — complete)
    float4 xv0 = a0 ? d_xn[i0] : make_float4(0, 0, 0, 0);
    float4 xv1 = b1 ? d_xn[i1] : make_float4(0, 0, 0, 0);
    float di0 = a0 ? d_dinv[i0] : 1.f;
    float di1 = b1 ? d_dinv[i1] : 1.f;
    GDC_WAIT();
    if (blockIdx.x == 0 && threadIdx.x < 4) {
        d_sum[threadIdx.x] = 0.0;
        d_sumsq[threadIdx.x] = 0.0;
    }
    float4 aa0 = a0 ? d_a1[i0] : make_float4(0, 0, 0, 0);
    float4 aa1 = b1 ? d_a1[i1] : make_float4(0, 0, 0, 0);
    if (a0) {
        float di2 = di0 * di0, di3 = di2 * di0;
        half2 h01 = __floats2half2_rn(aa0.x * di2 + xv0.x * di3,
                                      aa0.y * di2 + xv0.y * di3);
        half2 h23 = __floats2half2_rn(aa0.z * di2 + xv0.z * di3,
                                      aa0.w * di2 + xv0.w * di3);
        d_a1[i0] = make_float4(0.f, 0.f, 0.f, 0.f);
        float4 p;
        p.x = *reinterpret_cast<float*>(&h01);
        p.y = *reinterpret_cast<float*>(&h23);
        p.z = di0;
        p.w = 0.f;
        d_zp[i0] = p;
    }
    if (b1) {
        float di2 = di1 * di1, di3 = di2 * di1;
        half2 h01 = __floats2half2_rn(aa1.x * di2 + xv1.x * di3,
                                      aa1.y * di2 + xv1.y * di3);
        half2 h23 = __floats2half2_rn(aa1.z * di2 + xv1.z * di3,
                                      aa1.w * di2 + xv1.w * di3);
        d_a1[i1] = make_float4(0.f, 0.f, 0.f, 0.f);
        float4 p;
        p.x = *reinterpret_cast<float*>(&h01);
        p.y = *reinterpret_cast<float*>(&h23);
        p.z = di1;
        p.w = 0.f;
        d_zp[i1] = p;
    }
    GDC_LAUNCH();
}

// m[d] += z[s]; n-channel only when conv1 bias nonzero; prelude: index loads
__global__ void __launch_bounds__(256) k_edge2(const int* __restrict__ ei) {
    int t = blockIdx.x * blockDim.x + threadIdx.x;
    bool act = (t < NE / 8);
    int tt = act ? t : 0;
    const int4* sp = (const int4*)ei;
    const int4* dp = (const int4*)(ei + NE);
    int4 s0 = sp[2 * tt], s1 = sp[2 * tt + 1];   // prelude
    int4 d0 = dp[2 * tt], d1 = dp[2 * tt + 1];   // prelude
    GDC_WAIT();
    if (act) {
        int needn = d_needn;
        float4 p0 = d_zp[s0.x];
        float4 p1 = d_zp[s0.y];
        float4 p2 = d_zp[s0.z];
        float4 p3 = d_zp[s0.w];
        float4 p4 = d_zp[s1.x];
        float4 p5 = d_zp[s1.y];
        float4 p6 = d_zp[s1.z];
        float4 p7 = d_zp[s1.w];
        #define E2_M(p, dd) do {                                              \
            float2 _z01 = __half22float2(*reinterpret_cast<half2*>(&(p).x));  \
            float2 _z23 = __half22float2(*reinterpret_cast<half2*>(&(p).y));  \
            red4(&d_m[dd], _z01.x, _z01.y, _z23.x, _z23.y);                   \
        } while (0)
        E2_M(p0, d0.x);
        E2_M(p1, d0.y);
        E2_M(p2, d0.z);
        E2_M(p3, d0.w);
        E2_M(p4, d1.x);
        E2_M(p5, d1.y);
        E2_M(p6, d1.z);
        E2_M(p7, d1.w);
        #undef E2_M
        if (needn) {
            red1(&d_n[d0.x], p0.z);
            red1(&d_n[d0.y], p1.z);
            red1(&d_n[d0.z], p2.z);
            red1(&d_n[d0.w], p3.z);
            red1(&d_n[d1.x], p4.z);
            red1(&d_n[d1.y], p5.z);
            red1(&d_n[d1.z], p6.z);
            red1(&d_n[d1.w], p7.z);
        }
    }
    GDC_LAUNCH();
}

// per-graph reduction; resets node accumulators
#define NCOPY 8
__global__ void __launch_bounds__(256) k_node3(const int* __restrict__ batch) {
    __shared__ float sacc[NCOPY][NG * 6];
    for (int j = threadIdx.x; j < NCOPY * NG * 6; j += blockDim.x)
        ((float*)sacc)[j] = 0.f;
    __syncthreads();
    GDC_WAIT();
    int w = (threadIdx.x >> 5) & (NCOPY - 1);
    int stride = gridDim.x * blockDim.x;
    const float4 z4 = make_float4(0.f, 0.f, 0.f, 0.f);
    for (int i = blockIdx.x * blockDim.x + threadIdx.x; i < NN; i += stride) {
        float4 p = d_zp[i];
        float4 m = d_m[i];
        float n = d_n[i];
        int g = batch[i];
        d_m[i] = z4;
        d_n[i] = 0.f;
        d_degx[i] = 0.f;
        float di = p.z;
        float2 z01 = __half22float2(*reinterpret_cast<half2*>(&p.x));
        float2 z23 = __half22float2(*reinterpret_cast<half2*>(&p.y));
        float* pp = &sacc[w][g * 6];
        atomicAdd(pp + 0, di * (m.x + z01.x));
        atomicAdd(pp + 1, di * (m.y + z01.y));
        atomicAdd(pp + 2, di * (m.z + z23.x));
        atomicAdd(pp + 3, di * (m.w + z23.y));
        atomicAdd(pp + 4, di * (n + di));
        atomicAdd(pp + 5, 1.0f);
    }
    __syncthreads();
    for (int j = threadIdx.x; j < NG * 6; j += blockDim.x) {
        float v = 0.f;
        #pragma unroll
        for (int k = 0; k < NCOPY; k++) v += sacc[k][j];
        int g = j / 6, c = j % 6;
        red1(&d_acc[g * 8 + c], v);
    }
    GDC_LAUNCH();
}

// One block, 64 threads: W0/W1 apply, BN1, MLP; resets d_acc
__global__ void k_final(const float* __restrict__ W0, const float* __restrict__ b0,
                        const float* __restrict__ W1, const float* __restrict__ b1,
                        const float* __restrict__ bn1g, const float* __restrict__ bn1b,
                        const float* __restrict__ l0W, const float* __restrict__ l0b,
                        const float* __restrict__ l1W, const float* __restrict__ l1b,
                        const float* __restrict__ oW, const float* __restrict__ ob,
                        float* __restrict__ out) {
    __shared__ float sg[64][65];
    __shared__ float sW[64 * 64];
    int t = threadIdx.x;

    for (int j = t; j < 4096; j += 64) sW[j] = W1[j];   // prelude (input)
    GDC_WAIT();

    float* acc = &d_acc[t * 8];
    float s4[4];
    #pragma unroll
    for (int c = 0; c < 4; c++) s4[c] = acc[c];
    float ss = acc[4];
    float ng = acc[5];
    #pragma unroll
    for (int c = 0; c < 8; c++) acc[c] = 0.f;

    float h[64];
    #pragma unroll
    for (int j = 0; j < 64; j++)
        h[j] = ss * b0[j] + s4[0] * W0[j] + s4[1] * W0[64 + j]
             + s4[2] * W0[128 + j] + s4[3] * W0[192 + j];
    __syncthreads();

    for (int j = 0; j < 64; j++) {
        float a = ng * b1[j];
        #pragma unroll
        for (int k = 0; k < 64; k++) a += h[k] * sW[k * 64 + j];
        sg[t][j] = a;
    }
    __syncthreads();

    {
        float m = 0.f;
        for (int G = 0; G < 64; G++) m += sg[G][t];
        m *= (1.0f / 64.0f);
        float v = 0.f;
        for (int G = 0; G < 64; G++) { float d = sg[G][t] - m; v += d * d; }
        v *= (1.0f / 64.0f);
        float r = rsqrtf(v + EPS) * bn1g[t];
        float bb = bn1b[t];
        for (int G = 0; G < 64; G++) sg[G][t] = (sg[G][t] - m) * r + bb;
    }
    __syncthreads();

    float h2[64];
    #pragma unroll
    for (int k = 0; k < 64; k++) h2[k] = sg[t][k];
    __syncthreads();
    for (int j = t; j < 4096; j += 64) sW[j] = l0W[j];
    __syncthreads();
    for (int j = 0; j < 64; j++) {
        float a = l0b[j];
        #pragma unroll
        for (int k = 0; k < 64; k++) a += h2[k] * sW[k * 64 + j];
        sg[t][j] = a;
    }
    __syncthreads();

    #pragma unroll
    for (int k = 0; k < 64; k++) h2[k] = sg[t][k];
    __syncthreads();
    for (int j = t; j < 4096; j += 64) sW[j] = l1W[j];
    __syncthreads();
    float o = ob[0];
    for (int j = 0; j < 64; j++) {
        float a = l1b[j];
        #pragma unroll
        for (int k = 0; k < 64; k++) a += h2[k] * sW[k * 64 + j];
        o += a * oW[j];
    }
    out[t] = o;
}

static void launch_pdl(const void* fn, dim3 grid, dim3 block, void** args) {
    cudaLaunchConfig_t cfg = {};
    cfg.gridDim = grid;
    cfg.blockDim = block;
    cfg.dynamicSmemBytes = 0;
    cfg.stream = 0;
    cudaLaunchAttribute at[1];
    at[0].id = cudaLaunchAttributeProgrammaticStreamSerialization;
    at[0].val.programmaticStreamSerializationAllowed = 1;
    cfg.attrs = at;
    cfg.numAttrs = 1;
    cudaLaunchKernelExC(&cfg, fn, args);
}

extern "C" void kernel_launch(void* const* d_in, const int* in_sizes, int n_in,
                              void* d_out, int out_size) {
    const float* x     = (const float*)d_in[0];
    const int*   ei    = (const int*)d_in[1];
    const int*   batch = (const int*)d_in[2];
    const float* bn0g = (const float*)d_in[3];
    const float* bn0b = (const float*)d_in[4];
    const float* W0   = (const float*)d_in[5];
    const float* b0   = (const float*)d_in[6];
    const float* W1   = (const float*)d_in[7];
    const float* b1   = (const float*)d_in[8];
    const float* bn1g = (const float*)d_in[9];
    const float* bn1b = (const float*)d_in[10];
    const float* l0W  = (const float*)d_in[11];
    const float* l0b  = (const float*)d_in[12];
    const float* l1W  = (const float*)d_in[13];
    const float* l1b  = (const float*)d_in[14];
    const float* oW   = (const float*)d_in[15];
    const float* ob   = (const float*)d_in[16];
    float* out = (float*)d_out;

    int et8 = NE / 8;                       // 400K edge threads
    dim3 b256(256);
    dim3 gE((et8 + 255) / 256);             // 1563
    dim3 gN((NN + 255) / 256);              // 391
    dim3 gN2((NN / 2 + 255) / 256);         // 196

    { void* a[] = {(void*)&x, (void*)&ei};
      launch_pdl((const void*)k_pre, gE, b256, a); }
    { void* a[] = {(void*)&x, (void*)&bn0g, (void*)&bn0b, (void*)&b0};
      launch_pdl((const void*)k_node1, gN, b256, a); }
    { void* a[] = {(void*)&ei};
      launch_pdl((const void*)k_edge1, gE, b256, a); }
    { void* a[] = {};
      launch_pdl((const void*)k_node2, gN2, b256, (void**)a); }
    { void* a[] = {(void*)&ei};
      launch_pdl((const void*)k_edge2, gE, b256, a); }
    { void* a[] = {(void*)&batch};
      launch_pdl((const void*)k_node3, dim3(148), b256, a); }
    { void* a[] = {(void*)&W0, (void*)&b0, (void*)&W1, (void*)&b1,
                   (void*)&bn1g, (void*)&bn1b, (void*)&l0W, (void*)&l0b,
                   (void*)&l1W, (void*)&l1b, (void*)&oW, (void*)&ob, (void*)&out};
      launch_pdl((const void*)k_final, dim3(1), dim3(64), a); }
}

// round 12
// speedup vs baseline: 2.8705x; 1.3088x over previous
#include <cuda_runtime.h>
#include <cuda_fp16.h>

#define NN 100000
#define NE 3200000
#define NG 64
#define EPS 1e-5f

#define GDC_WAIT()   asm volatile("griddepcontrol.wait;" ::: "memory")
#define GDC_LAUNCH() asm volatile("griddepcontrol.launch_dependents;" ::: "memory")

// Scratch (__device__ globals; accumulators zero at rest; each kernel that
// last reads one resets it for the next graph replay).
__device__ float4 d_xn[NN];
__device__ float4 d_y[NN];
__device__ float4 d_a1[NN];     // raw agg accumulator (reset in node2)
__device__ float4 d_zp[NN];     // packed {half2 z01, half2 z23, f32 dinv, pad}
__device__ float4 d_m[NN];      // layer2 v4 accumulator (reset in node3)
__device__ float  d_n[NN];      // layer2 scalar accumulator (reset in node3 when used)
__device__ float  d_degx[NN];   // degree-1 (reset in node3)
__device__ float  d_dinv[NN];
__device__ double d_sum[4];     // reset in node2
__device__ double d_sumsq[4];   // reset in node2
__device__ int    d_needn;      // 1 iff conv1 bias b0 nonzero
__device__ float  d_acc[NG * 8];// per graph: [0..3]=s4,[4]=ss,[5]=ng; reset in final

__device__ __forceinline__ void red4(float4* p, float a, float b, float c, float d) {
    asm volatile("red.global.add.v4.f32 [%0], {%1,%2,%3,%4};"
                 :: "l"(p), "f"(a), "f"(b), "f"(c), "f"(d) : "memory");
}
__device__ __forceinline__ void red4v(float4* p, float4 v) {
    asm volatile("red.global.add.v4.f32 [%0], {%1,%2,%3,%4};"
                 :: "l"(p), "f"(v.x), "f"(v.y), "f"(v.z), "f"(v.w) : "memory");
}
__device__ __forceinline__ void red1(float* p, float a) {
    asm volatile("red.global.add.f32 [%0], %1;" :: "l"(p), "f"(a) : "memory");
}

// Fused: degree accumulation (8 edges/thread) + BN0 statistics
__global__ void __launch_bounds__(256) k_pre(const float* __restrict__ x,
                                             const int* __restrict__ ei) {
    int t = blockIdx.x * blockDim.x + threadIdx.x;
    if (t < NE / 8) {
        const int4* dp = (const int4*)(ei + NE);
        int4 d0 = dp[2 * t];
        int4 d1 = dp[2 * t + 1];
        red1(&d_degx[d0.x], 1.0f);
        red1(&d_degx[d0.y], 1.0f);
        red1(&d_degx[d0.z], 1.0f);
        red1(&d_degx[d0.w], 1.0f);
        red1(&d_degx[d1.x], 1.0f);
        red1(&d_degx[d1.y], 1.0f);
        red1(&d_degx[d1.z], 1.0f);
        red1(&d_degx[d1.w], 1.0f);
    }
    if (blockIdx.x < 256) {
        int j0 = blockIdx.x * blockDim.x + threadIdx.x;
        int stride = 256 * blockDim.x;
        double s0 = 0, s1 = 0, s2 = 0, s3 = 0;
        double q0 = 0, q1 = 0, q2 = 0, q3 = 0;
        for (int j = j0; j < NN; j += stride) {
            float4 v = ((const float4*)x)[j];
            s0 += v.x; q0 += (double)v.x * v.x;
            s1 += v.y; q1 += (double)v.y * v.y;
            s2 += v.z; q2 += (double)v.z * v.z;
            s3 += v.w; q3 += (double)v.w * v.w;
        }
        #pragma unroll
        for (int o = 16; o > 0; o >>= 1) {
            s0 += __shfl_down_sync(0xffffffffu, s0, o);
            s1 += __shfl_down_sync(0xffffffffu, s1, o);
            s2 += __shfl_down_sync(0xffffffffu, s2, o);
            s3 += __shfl_down_sync(0xffffffffu, s3, o);
            q0 += __shfl_down_sync(0xffffffffu, q0, o);
            q1 += __shfl_down_sync(0xffffffffu, q1, o);
            q2 += __shfl_down_sync(0xffffffffu, q2, o);
            q3 += __shfl_down_sync(0xffffffffu, q3, o);
        }
        if ((threadIdx.x & 31) == 0) {
            atomicAdd(&d_sum[0], s0); atomicAdd(&d_sumsq[0], q0);
            atomicAdd(&d_sum[1], s1); atomicAdd(&d_sumsq[1], q1);
            atomicAdd(&d_sum[2], s2); atomicAdd(&d_sumsq[2], q2);
            atomicAdd(&d_sum[3], s3); atomicAdd(&d_sumsq[3], q3);
        }
    }
    GDC_LAUNCH();
}

// BN0 normalize + dinv + y; 2 nodes/thread; prelude: x loads
__global__ void __launch_bounds__(256) k_node1(const float* __restrict__ x,
                                               const float* __restrict__ g0,
                                               const float* __restrict__ b0,
                                               const float* __restrict__ b0c) {
    __shared__ float sbn[12];
    int t = blockIdx.x * blockDim.x + threadIdx.x;
    int i0 = 2 * t, i1 = 2 * t + 1;
    bool a0 = (i0 < NN), a1 = (i1 < NN);
    float4 v0 = a0 ? ((const float4*)x)[i0] : make_float4(0, 0, 0, 0);  // prelude
    float4 v1 = a1 ? ((const float4*)x)[i1] : make_float4(0, 0, 0, 0);  // prelude
    GDC_WAIT();
    if (threadIdx.x == 0) {
        #pragma unroll
        for (int c = 0; c < 4; c++) {
            double m = d_sum[c] / (double)NN;
            double var = d_sumsq[c] / (double)NN - m * m;
            sbn[c] = (float)m;
            sbn[4 + c] = rsqrtf((float)var + EPS) * g0[c];
            sbn[8 + c] = b0[c];
        }
        if (blockIdx.x == 0) {
            float mx = 0.f;
            for (int j = 0; j < 64; j++) mx = fmaxf(mx, fabsf(b0c[j]));
            d_needn = (mx > 0.f) ? 1 : 0;
        }
    }
    __syncthreads();
    float dg0 = a0 ? d_degx[i0] : 0.f;
    float dg1 = a1 ? d_degx[i1] : 0.f;
    if (a0) {
        float4 o;
        o.x = (v0.x - sbn[0]) * sbn[4] + sbn[8];
        o.y = (v0.y - sbn[1]) * sbn[5] + sbn[9];
        o.z = (v0.z - sbn[2]) * sbn[6] + sbn[10];
        o.w = (v0.w - sbn[3]) * sbn[7] + sbn[11];
        d_xn[i0] = o;
        float di = rsqrtf(dg0 + 1.0f);
        d_dinv[i0] = di;
        d_y[i0] = make_float4(o.x * di, o.y * di, o.z * di, o.w * di);
    }
    if (a1) {
        float4 o;
        o.x = (v1.x - sbn[0]) * sbn[4] + sbn[8];
        o.y = (v1.y - sbn[1]) * sbn[5] + sbn[9];
        o.z = (v1.z - sbn[2]) * sbn[6] + sbn[10];
        o.w = (v1.w - sbn[3]) * sbn[7] + sbn[11];
        d_xn[i1] = o;
        float di = rsqrtf(dg1 + 1.0f);
        d_dinv[i1] = di;
        d_y[i1] = make_float4(o.x * di, o.y * di, o.z * di, o.w * di);
    }
    GDC_LAUNCH();
}

// agg_raw[d] += y[s], 8 edges/thread; prelude: index loads
__global__ void __launch_bounds__(256) k_edge1(const int* __restrict__ ei) {
    int t = blockIdx.x * blockDim.x + threadIdx.x;
    bool act = (t < NE / 8);
    int tt = act ? t : 0;
    const int4* sp = (const int4*)ei;
    const int4* dp = (const int4*)(ei + NE);
    int4 s0 = sp[2 * tt], s1 = sp[2 * tt + 1];
    int4 d0 = dp[2 * tt], d1 = dp[2 * tt + 1];
    GDC_WAIT();
    if (act) {
        float4 y0 = d_y[s0.x];
        float4 y1 = d_y[s0.y];
        float4 y2 = d_y[s0.z];
        float4 y3 = d_y[s0.w];
        float4 y4 = d_y[s1.x];
        float4 y5 = d_y[s1.y];
        float4 y6 = d_y[s1.z];
        float4 y7 = d_y[s1.w];
        red4v(&d_a1[d0.x], y0);
        red4v(&d_a1[d0.y], y1);
        red4v(&d_a1[d0.z], y2);
        red4v(&d_a1[d0.w], y3);
        red4v(&d_a1[d1.x], y4);
        red4v(&d_a1[d1.y], y5);
        red4v(&d_a1[d1.z], y6);
        red4v(&d_a1[d1.w], y7);
    }
    GDC_LAUNCH();
}

// z = di^2*agg_raw + di^3*xn, packed; 2 nodes/thread; resets d_a1 and BN sums
__global__ void __launch_bounds__(256) k_node2() {
    int t = blockIdx.x * blockDim.x + threadIdx.x;
    int i0 = 2 * t, i1 = 2 * t + 1;
    bool a0 = (i0 < NN), b1 = (i1 < NN);
    float4 xv0 = a0 ? d_xn[i0] : make_float4(0, 0, 0, 0);
    float4 xv1 = b1 ? d_xn[i1] : make_float4(0, 0, 0, 0);
    float di0 = a0 ? d_dinv[i0] : 1.f;
    float di1 = b1 ? d_dinv[i1] : 1.f;
    GDC_WAIT();
    if (blockIdx.x == 0 && threadIdx.x < 4) {
        d_sum[threadIdx.x] = 0.0;
        d_sumsq[threadIdx.x] = 0.0;
    }
    float4 aa0 = a0 ? d_a1[i0] : make_float4(0, 0, 0, 0);
    float4 aa1 = b1 ? d_a1[i1] : make_float4(0, 0, 0, 0);
    if (a0) {
        float di2 = di0 * di0, di3 = di2 * di0;
        half2 h01 = __floats2half2_rn(aa0.x * di2 + xv0.x * di3,
                                      aa0.y * di2 + xv0.y * di3);
        half2 h23 = __floats2half2_rn(aa0.z * di2 + xv0.z * di3,
                                      aa0.w * di2 + xv0.w * di3);
        d_a1[i0] = make_float4(0.f, 0.f, 0.f, 0.f);
        float4 p;
        p.x = *reinterpret_cast<float*>(&h01);
        p.y = *reinterpret_cast<float*>(&h23);
        p.z = di0;
        p.w = 0.f;
        d_zp[i0] = p;
    }
    if (b1) {
        float di2 = di1 * di1, di3 = di2 * di1;
        half2 h01 = __floats2half2_rn(aa1.x * di2 + xv1.x * di3,
                                      aa1.y * di2 + xv1.y * di3);
        half2 h23 = __floats2half2_rn(aa1.z * di2 + xv1.z * di3,
                                      aa1.w * di2 + xv1.w * di3);
        d_a1[i1] = make_float4(0.f, 0.f, 0.f, 0.f);
        float4 p;
        p.x = *reinterpret_cast<float*>(&h01);
        p.y = *reinterpret_cast<float*>(&h23);
        p.z = di1;
        p.w = 0.f;
        d_zp[i1] = p;
    }
    GDC_LAUNCH();
}

// m[d] += z[s]; n-channel only when conv1 bias nonzero; prelude: index loads
__global__ void __launch_bounds__(256) k_edge2(const int* __restrict__ ei) {
    int t = blockIdx.x * blockDim.x + threadIdx.x;
    bool act = (t < NE / 8);
    int tt = act ? t : 0;
    const int4* sp = (const int4*)ei;
    const int4* dp = (const int4*)(ei + NE);
    int4 s0 = sp[2 * tt], s1 = sp[2 * tt + 1];
    int4 d0 = dp[2 * tt], d1 = dp[2 * tt + 1];
    GDC_WAIT();
    if (act) {
        int needn = d_needn;
        float4 p0 = d_zp[s0.x];
        float4 p1 = d_zp[s0.y];
        float4 p2 = d_zp[s0.z];
        float4 p3 = d_zp[s0.w];
        float4 p4 = d_zp[s1.x];
        float4 p5 = d_zp[s1.y];
        float4 p6 = d_zp[s1.z];
        float4 p7 = d_zp[s1.w];
        #define E2_M(p, dd) do {                                              \
            float2 _z01 = __half22float2(*reinterpret_cast<half2*>(&(p).x));  \
            float2 _z23 = __half22float2(*reinterpret_cast<half2*>(&(p).y));  \
            red4(&d_m[dd], _z01.x, _z01.y, _z23.x, _z23.y);                   \
        } while (0)
        E2_M(p0, d0.x);
        E2_M(p1, d0.y);
        E2_M(p2, d0.z);
        E2_M(p3, d0.w);
        E2_M(p4, d1.x);
        E2_M(p5, d1.y);
        E2_M(p6, d1.z);
        E2_M(p7, d1.w);
        #undef E2_M
        if (needn) {
            red1(&d_n[d0.x], p0.z);
            red1(&d_n[d0.y], p1.z);
            red1(&d_n[d0.z], p2.z);
            red1(&d_n[d0.w], p3.z);
            red1(&d_n[d1.x], p4.z);
            red1(&d_n[d1.y], p5.z);
            red1(&d_n[d1.z], p6.z);
            red1(&d_n[d1.w], p7.z);
        }
    }
    GDC_LAUNCH();
}

// per-graph reduction; resets node accumulators; n-channel gated on d_needn
#define NCOPY 8
__global__ void __launch_bounds__(256) k_node3(const int* __restrict__ batch) {
    __shared__ float sacc[NCOPY][NG * 6];
    for (int j = threadIdx.x; j < NCOPY * NG * 6; j += blockDim.x)
        ((float*)sacc)[j] = 0.f;
    __syncthreads();
    GDC_WAIT();
    int needn = d_needn;
    int w = (threadIdx.x >> 5) & (NCOPY - 1);
    int stride = gridDim.x * blockDim.x;
    const float4 z4 = make_float4(0.f, 0.f, 0.f, 0.f);
    for (int i = blockIdx.x * blockDim.x + threadIdx.x; i < NN; i += stride) {
        float4 p = d_zp[i];
        float4 m = d_m[i];
        int g = batch[i];
        d_m[i] = z4;
        d_degx[i] = 0.f;
        float di = p.z;
        float2 z01 = __half22float2(*reinterpret_cast<half2*>(&p.x));
        float2 z23 = __half22float2(*reinterpret_cast<half2*>(&p.y));
        float* pp = &sacc[w][g * 6];
        atomicAdd(pp + 0, di * (m.x + z01.x));
        atomicAdd(pp + 1, di * (m.y + z01.y));
        atomicAdd(pp + 2, di * (m.z + z23.x));
        atomicAdd(pp + 3, di * (m.w + z23.y));
        if (needn) {
            float n = d_n[i];
            d_n[i] = 0.f;
            atomicAdd(pp + 4, di * (n + di));
        }
        atomicAdd(pp + 5, 1.0f);
    }
    __syncthreads();
    for (int j = threadIdx.x; j < NG * 6; j += blockDim.x) {
        float v = 0.f;
        #pragma unroll
        for (int k = 0; k < NCOPY; k++) v += sacc[k][j];
        int g = j / 6, c = j % 6;
        red1(&d_acc[g * 8 + c], v);
    }
    GDC_LAUNCH();
}

// Rank-7 tail: the whole W0→W1→BN1→lin0→lin1→out pipeline operates on the
// 7-vector c_g = (s4[0..3], ss, ng, 1) per graph. BN1 stats come from the 7x7
// second-moment matrix S (exact re-association of the biased variance).
__global__ void __launch_bounds__(256) k_final(
        const float* __restrict__ W0, const float* __restrict__ b0,
        const float* __restrict__ W1, const float* __restrict__ b1,
        const float* __restrict__ bn1g, const float* __restrict__ bn1b,
        const float* __restrict__ l0W, const float* __restrict__ l0b,
        const float* __restrict__ l1W, const float* __restrict__ l1b,
        const float* __restrict__ oW, const float* __restrict__ ob,
        float* __restrict__ out) {
    __shared__ float sW[4096];      // current 64x64 weight
    __shared__ float sB[5][64];     // rows: W0[0..3][k], b0[k]
    __shared__ float sA[2][7][68];  // ping-pong rank-7 matrices
    __shared__ float sC[7][64];     // c-vectors per graph
    __shared__ float sS[7][7];      // second moments
    __shared__ float swv[8];        // output weights per c
    int t = threadIdx.x;

    // prelude (inputs only)
    for (int j = t; j < 4096; j += 256) sW[j] = W1[j];
    if (t < 256) ((float*)sB)[t] = W0[t];
    if (t >= 192 && t < 256) sB[4][t - 192] = b0[t - 192];
    GDC_WAIT();

    // read + reset per-graph accumulators
    if (t < 64) {
        float* acc = &d_acc[t * 8];
        sC[0][t] = acc[0];
        sC[1][t] = acc[1];
        sC[2][t] = acc[2];
        sC[3][t] = acc[3];
        sC[4][t] = acc[4];
        sC[5][t] = acc[5];
        sC[6][t] = 1.0f;
        #pragma unroll
        for (int c = 0; c < 8; c++) acc[c] = 0.f;
    }
    __syncthreads();

    // A1 = [W0;b0] @ W1 (rows 0..4); row5 = b1; row6 = 0
    for (int task = t; task < 320; task += 256) {
        int c = task >> 6, j = task & 63;
        float a = 0.f;
        #pragma unroll
        for (int k = 0; k < 64; k++) a += sB[c][k] * sW[k * 64 + j];
        sA[0][c][j] = a;
    }
    if (t < 64) {
        sA[0][5][t] = b1[t];
        sA[0][6][t] = 0.f;
    }
    // S[a][b] = sum_g c_g[a] c_g[b]
    if (t < 49) {
        int a = t / 7, b = t % 7;
        float s = 0.f;
        #pragma unroll
        for (int g = 0; g < 64; g++) s += sC[a][g] * sC[b][g];
        sS[a][b] = s;
    }
    __syncthreads();

    // BN1 per output feature j (thread j<64): mu, var from S; scale columns
    if (t < 64) {
        int j = t;
        float aj[7];
        #pragma unroll
        for (int c = 0; c < 7; c++) aj[c] = sA[0][c][j];
        float mu = 0.f;
        #pragma unroll
        for (int c = 0; c < 7; c++) mu += sS[c][6] * aj[c];
        mu *= (1.0f / 64.0f);
        float msq = 0.f;
        #pragma unroll
        for (int a = 0; a < 7; a++) {
            float inner = 0.f;
            #pragma unroll
            for (int b = 0; b < 7; b++) inner += sS[a][b] * aj[b];
            msq += aj[a] * inner;
        }
        msq *= (1.0f / 64.0f);
        float var = msq - mu * mu;
        float r = rsqrtf(var + EPS) * bn1g[j];
        #pragma unroll
        for (int c = 0; c < 7; c++) sA[0][c][j] = aj[c] * r;
        sA[0][6][j] += bn1b[j] - mu * r;
    }
    __syncthreads();

    // lin0: A3 = A2 @ l0W, row6 += l0b
    for (int j = t; j < 4096; j += 256) sW[j] = l0W[j];
    __syncthreads();
    for (int task = t; task < 448; task += 256) {
        int c = task / 64, j = task & 63;
        float a = 0.f;
        #pragma unroll
        for (int k = 0; k < 64; k++) a += sA[0][c][k] * sW[k * 64 + j];
        if (c == 6) a += l0b[j];
        sA[1][c][j] = a;
    }
    __syncthreads();

    // lin1: A4 = A3 @ l1W, row6 += l1b
    for (int j = t; j < 4096; j += 256) sW[j] = l1W[j];
    __syncthreads();
    for (int task = t; task < 448; task += 256) {
        int c = task / 64, j = task & 63;
        float a = 0.f;
        #pragma unroll
        for (int k = 0; k < 64; k++) a += sA[1][c][k] * sW[k * 64 + j];
        if (c == 6) a += l1b[j];
        sA[0][c][j] = a;
    }
    __syncthreads();

    // out: w[c] = A4[c] . oW ; out[g] = ob + c_g . w
    if (t < 7) {
        float s = 0.f;
        #pragma unroll
        for (int j = 0; j < 64; j++) s += sA[0][t][j] * oW[j];
        swv[t] = s;
    }
    __syncthreads();
    if (t < 64) {
        float o = ob[0];
        #pragma unroll
        for (int c = 0; c < 7; c++) o += sC[c][t] * swv[c];
        out[t] = o;
    }
}

static void launch_pdl(const void* fn, dim3 grid, dim3 block, void** args) {
    cudaLaunchConfig_t cfg = {};
    cfg.gridDim = grid;
    cfg.blockDim = block;
    cfg.dynamicSmemBytes = 0;
    cfg.stream = 0;
    cudaLaunchAttribute at[1];
    at[0].id = cudaLaunchAttributeProgrammaticStreamSerialization;
    at[0].val.programmaticStreamSerializationAllowed = 1;
    cfg.attrs = at;
    cfg.numAttrs = 1;
    cudaLaunchKernelExC(&cfg, fn, args);
}

extern "C" void kernel_launch(void* const* d_in, const int* in_sizes, int n_in,
                              void* d_out, int out_size) {
    const float* x     = (const float*)d_in[0];
    const int*   ei    = (const int*)d_in[1];
    const int*   batch = (const int*)d_in[2];
    const float* bn0g = (const float*)d_in[3];
    const float* bn0b = (const float*)d_in[4];
    const float* W0   = (const float*)d_in[5];
    const float* b0   = (const float*)d_in[6];
    const float* W1   = (const float*)d_in[7];
    const float* b1   = (const float*)d_in[8];
    const float* bn1g = (const float*)d_in[9];
    const float* bn1b = (const float*)d_in[10];
    const float* l0W  = (const float*)d_in[11];
    const float* l0b  = (const float*)d_in[12];
    const float* l1W  = (const float*)d_in[13];
    const float* l1b  = (const float*)d_in[14];
    const float* oW   = (const float*)d_in[15];
    const float* ob   = (const float*)d_in[16];
    float* out = (float*)d_out;

    int et8 = NE / 8;                       // 400K edge threads
    dim3 b256(256);
    dim3 gE((et8 + 255) / 256);             // 1563
    dim3 gN2((NN / 2 + 255) / 256);         // 196

    { void* a[] = {(void*)&x, (void*)&ei};
      launch_pdl((const void*)k_pre, gE, b256, a); }
    { void* a[] = {(void*)&x, (void*)&bn0g, (void*)&bn0b, (void*)&b0};
      launch_pdl((const void*)k_node1, gN2, b256, a); }
    { void* a[] = {(void*)&ei};
      launch_pdl((const void*)k_edge1, gE, b256, a); }
    { void* a[] = {};
      launch_pdl((const void*)k_node2, gN2, b256, (void**)a); }
    { void* a[] = {(void*)&ei};
      launch_pdl((const void*)k_edge2, gE, b256, a); }
    { void* a[] = {(void*)&batch};
      launch_pdl((const void*)k_node3, dim3(148), b256, a); }
    { void* a[] = {(void*)&W0, (void*)&b0, (void*)&W1, (void*)&b1,
                   (void*)&bn1g, (void*)&bn1b, (void*)&l0W, (void*)&l0b,
                   (void*)&l1W, (void*)&l1b, (void*)&oW, (void*)&ob, (void*)&out};
      launch_pdl((const void*)k_final, dim3(1), b256, a); }
}

// round 13
// speedup vs baseline: 2.8852x; 1.0051x over previous
#include <cuda_runtime.h>
#include <cuda_fp16.h>

#define NN 100000
#define NE 3200000
#define NG 64
#define EPS 1e-5f

#define GDC_WAIT()   asm volatile("griddepcontrol.wait;" ::: "memory")
#define GDC_LAUNCH() asm volatile("griddepcontrol.launch_dependents;" ::: "memory")

// Scratch (__device__ globals). d_a1 is fully overwritten by node1 each run
// (seeded with y) so it needs no zero-reset; d_m/d_n/d_degx/d_acc are
// accumulators reset by the last kernel that reads them.
__device__ float4 d_y[NN];      // dinv*xn (also the self-loop seed)
__device__ float4 d_a1[NN];     // seeded y_i by node1, then += y_s by edge1
__device__ float4 d_zp[NN];     // packed {half2 z01, half2 z23, f32 dinv, pad}
__device__ float4 d_m[NN];      // layer2 v4 accumulator (reset in node3)
__device__ float  d_n[NN];      // layer2 scalar accumulator (reset in node3 when used)
__device__ float  d_degx[NN];   // degree-1 (reset in node3)
__device__ float  d_dinv[NN];
__device__ double d_sum[4];     // reset in node2
__device__ double d_sumsq[4];   // reset in node2
__device__ int    d_needn;      // 1 iff conv1 bias b0 nonzero
__device__ float  d_acc[NG * 8];// per graph: [0..3]=s4,[4]=ss,[5]=ng; reset in final

__device__ __forceinline__ void red4(float4* p, float a, float b, float c, float d) {
    asm volatile("red.global.add.v4.f32 [%0], {%1,%2,%3,%4};"
                 :: "l"(p), "f"(a), "f"(b), "f"(c), "f"(d) : "memory");
}
__device__ __forceinline__ void red4v(float4* p, float4 v) {
    asm volatile("red.global.add.v4.f32 [%0], {%1,%2,%3,%4};"
                 :: "l"(p), "f"(v.x), "f"(v.y), "f"(v.z), "f"(v.w) : "memory");
}
__device__ __forceinline__ void red1(float* p, float a) {
    asm volatile("red.global.add.f32 [%0], %1;" :: "l"(p), "f"(a) : "memory");
}

// Fused: degree accumulation (8 edges/thread) + BN0 statistics
__global__ void __launch_bounds__(256) k_pre(const float* __restrict__ x,
                                             const int* __restrict__ ei) {
    int t = blockIdx.x * blockDim.x + threadIdx.x;
    if (t < NE / 8) {
        const int4* dp = (const int4*)(ei + NE);
        int4 d0 = dp[2 * t];
        int4 d1 = dp[2 * t + 1];
        red1(&d_degx[d0.x], 1.0f);
        red1(&d_degx[d0.y], 1.0f);
        red1(&d_degx[d0.z], 1.0f);
        red1(&d_degx[d0.w], 1.0f);
        red1(&d_degx[d1.x], 1.0f);
        red1(&d_degx[d1.y], 1.0f);
        red1(&d_degx[d1.z], 1.0f);
        red1(&d_degx[d1.w], 1.0f);
    }
    if (blockIdx.x < 256) {
        int j0 = blockIdx.x * blockDim.x + threadIdx.x;
        int stride = 256 * blockDim.x;
        double s0 = 0, s1 = 0, s2 = 0, s3 = 0;
        double q0 = 0, q1 = 0, q2 = 0, q3 = 0;
        for (int j = j0; j < NN; j += stride) {
            float4 v = ((const float4*)x)[j];
            s0 += v.x; q0 += (double)v.x * v.x;
            s1 += v.y; q1 += (double)v.y * v.y;
            s2 += v.z; q2 += (double)v.z * v.z;
            s3 += v.w; q3 += (double)v.w * v.w;
        }
        #pragma unroll
        for (int o = 16; o > 0; o >>= 1) {
            s0 += __shfl_down_sync(0xffffffffu, s0, o);
            s1 += __shfl_down_sync(0xffffffffu, s1, o);
            s2 += __shfl_down_sync(0xffffffffu, s2, o);
            s3 += __shfl_down_sync(0xffffffffu, s3, o);
            q0 += __shfl_down_sync(0xffffffffu, q0, o);
            q1 += __shfl_down_sync(0xffffffffu, q1, o);
            q2 += __shfl_down_sync(0xffffffffu, q2, o);
            q3 += __shfl_down_sync(0xffffffffu, q3, o);
        }
        if ((threadIdx.x & 31) == 0) {
            atomicAdd(&d_sum[0], s0); atomicAdd(&d_sumsq[0], q0);
            atomicAdd(&d_sum[1], s1); atomicAdd(&d_sumsq[1], q1);
            atomicAdd(&d_sum[2], s2); atomicAdd(&d_sumsq[2], q2);
            atomicAdd(&d_sum[3], s3); atomicAdd(&d_sumsq[3], q3);
        }
    }
    GDC_LAUNCH();
}

// BN0 normalize + dinv + y; seeds d_a1 = y (self-loop term); 2 nodes/thread
__global__ void __launch_bounds__(256) k_node1(const float* __restrict__ x,
                                               const float* __restrict__ g0,
                                               const float* __restrict__ b0,
                                               const float* __restrict__ b0c) {
    __shared__ float sbn[12];
    int t = blockIdx.x * blockDim.x + threadIdx.x;
    int i0 = 2 * t, i1 = 2 * t + 1;
    bool a0 = (i0 < NN), a1 = (i1 < NN);
    float4 v0 = a0 ? ((const float4*)x)[i0] : make_float4(0, 0, 0, 0);  // prelude
    float4 v1 = a1 ? ((const float4*)x)[i1] : make_float4(0, 0, 0, 0);  // prelude
    GDC_WAIT();
    if (threadIdx.x == 0) {
        #pragma unroll
        for (int c = 0; c < 4; c++) {
            double m = d_sum[c] / (double)NN;
            double var = d_sumsq[c] / (double)NN - m * m;
            sbn[c] = (float)m;
            sbn[4 + c] = rsqrtf((float)var + EPS) * g0[c];
            sbn[8 + c] = b0[c];
        }
        if (blockIdx.x == 0) {
            float mx = 0.f;
            for (int j = 0; j < 64; j++) mx = fmaxf(mx, fabsf(b0c[j]));
            d_needn = (mx > 0.f) ? 1 : 0;
        }
    }
    __syncthreads();
    float dg0 = a0 ? d_degx[i0] : 0.f;
    float dg1 = a1 ? d_degx[i1] : 0.f;
    if (a0) {
        float di = rsqrtf(dg0 + 1.0f);
        float4 y;
        y.x = ((v0.x - sbn[0]) * sbn[4] + sbn[8]) * di;
        y.y = ((v0.y - sbn[1]) * sbn[5] + sbn[9]) * di;
        y.z = ((v0.z - sbn[2]) * sbn[6] + sbn[10]) * di;
        y.w = ((v0.w - sbn[3]) * sbn[7] + sbn[11]) * di;
        d_dinv[i0] = di;
        d_y[i0] = y;
        d_a1[i0] = y;      // self-loop seed: a1 = y_i + sum_s y_s
    }
    if (a1) {
        float di = rsqrtf(dg1 + 1.0f);
        float4 y;
        y.x = ((v1.x - sbn[0]) * sbn[4] + sbn[8]) * di;
        y.y = ((v1.y - sbn[1]) * sbn[5] + sbn[9]) * di;
        y.z = ((v1.z - sbn[2]) * sbn[6] + sbn[10]) * di;
        y.w = ((v1.w - sbn[3]) * sbn[7] + sbn[11]) * di;
        d_dinv[i1] = di;
        d_y[i1] = y;
        d_a1[i1] = y;
    }
    GDC_LAUNCH();
}

// a1[d] += y[s], 8 edges/thread; prelude: index loads
__global__ void __launch_bounds__(256) k_edge1(const int* __restrict__ ei) {
    int t = blockIdx.x * blockDim.x + threadIdx.x;
    bool act = (t < NE / 8);
    int tt = act ? t : 0;
    const int4* sp = (const int4*)ei;
    const int4* dp = (const int4*)(ei + NE);
    int4 s0 = sp[2 * tt], s1 = sp[2 * tt + 1];
    int4 d0 = dp[2 * tt], d1 = dp[2 * tt + 1];
    GDC_WAIT();
    if (act) {
        float4 y0 = d_y[s0.x];
        float4 y1 = d_y[s0.y];
        float4 y2 = d_y[s0.z];
        float4 y3 = d_y[s0.w];
        float4 y4 = d_y[s1.x];
        float4 y5 = d_y[s1.y];
        float4 y6 = d_y[s1.z];
        float4 y7 = d_y[s1.w];
        red4v(&d_a1[d0.x], y0);
        red4v(&d_a1[d0.y], y1);
        red4v(&d_a1[d0.z], y2);
        red4v(&d_a1[d0.w], y3);
        red4v(&d_a1[d1.x], y4);
        red4v(&d_a1[d1.y], y5);
        red4v(&d_a1[d1.z], y6);
        red4v(&d_a1[d1.w], y7);
    }
    GDC_LAUNCH();
}

// z = di^2 * a1 (a1 already contains self-loop), packed; 2 nodes/thread;
// resets BN sums. No xn load, no a1 reset (node1 overwrites it each run).
__global__ void __launch_bounds__(256) k_node2() {
    int t = blockIdx.x * blockDim.x + threadIdx.x;
    int i0 = 2 * t, i1 = 2 * t + 1;
    bool a0 = (i0 < NN), b1 = (i1 < NN);
    float di0 = a0 ? d_dinv[i0] : 1.f;   // prelude (node1 is 2 kernels back)
    float di1 = b1 ? d_dinv[i1] : 1.f;
    GDC_WAIT();
    if (blockIdx.x == 0 && threadIdx.x < 4) {
        d_sum[threadIdx.x] = 0.0;
        d_sumsq[threadIdx.x] = 0.0;
    }
    float4 aa0 = a0 ? d_a1[i0] : make_float4(0, 0, 0, 0);
    float4 aa1 = b1 ? d_a1[i1] : make_float4(0, 0, 0, 0);
    if (a0) {
        float di2 = di0 * di0;
        half2 h01 = __floats2half2_rn(aa0.x * di2, aa0.y * di2);
        half2 h23 = __floats2half2_rn(aa0.z * di2, aa0.w * di2);
        float4 p;
        p.x = *reinterpret_cast<float*>(&h01);
        p.y = *reinterpret_cast<float*>(&h23);
        p.z = di0;
        p.w = 0.f;
        d_zp[i0] = p;
    }
    if (b1) {
        float di2 = di1 * di1;
        half2 h01 = __floats2half2_rn(aa1.x * di2, aa1.y * di2);
        half2 h23 = __floats2half2_rn(aa1.z * di2, aa1.w * di2);
        float4 p;
        p.x = *reinterpret_cast<float*>(&h01);
        p.y = *reinterpret_cast<float*>(&h23);
        p.z = di1;
        p.w = 0.f;
        d_zp[i1] = p;
    }
    GDC_LAUNCH();
}

// m[d] += z[s]; n-channel only when conv1 bias nonzero; prelude: index loads
__global__ void __launch_bounds__(256) k_edge2(const int* __restrict__ ei) {
    int t = blockIdx.x * blockDim.x + threadIdx.x;
    bool act = (t < NE / 8);
    int tt = act ? t : 0;
    const int4* sp = (const int4*)ei;
    const int4* dp = (const int4*)(ei + NE);
    int4 s0 = sp[2 * tt], s1 = sp[2 * tt + 1];
    int4 d0 = dp[2 * tt], d1 = dp[2 * tt + 1];
    GDC_WAIT();
    if (act) {
        int needn = d_needn;
        float4 p0 = d_zp[s0.x];
        float4 p1 = d_zp[s0.y];
        float4 p2 = d_zp[s0.z];
        float4 p3 = d_zp[s0.w];
        float4 p4 = d_zp[s1.x];
        float4 p5 = d_zp[s1.y];
        float4 p6 = d_zp[s1.z];
        float4 p7 = d_zp[s1.w];
        #define E2_M(p, dd) do {                                              \
            float2 _z01 = __half22float2(*reinterpret_cast<half2*>(&(p).x));  \
            float2 _z23 = __half22float2(*reinterpret_cast<half2*>(&(p).y));  \
            red4(&d_m[dd], _z01.x, _z01.y, _z23.x, _z23.y);                   \
        } while (0)
        E2_M(p0, d0.x);
        E2_M(p1, d0.y);
        E2_M(p2, d0.z);
        E2_M(p3, d0.w);
        E2_M(p4, d1.x);
        E2_M(p5, d1.y);
        E2_M(p6, d1.z);
        E2_M(p7, d1.w);
        #undef E2_M
        if (needn) {
            red1(&d_n[d0.x], p0.z);
            red1(&d_n[d0.y], p1.z);
            red1(&d_n[d0.z], p2.z);
            red1(&d_n[d0.w], p3.z);
            red1(&d_n[d1.x], p4.z);
            red1(&d_n[d1.y], p5.z);
            red1(&d_n[d1.z], p6.z);
            red1(&d_n[d1.w], p7.z);
        }
    }
    GDC_LAUNCH();
}

// per-graph reduction; resets node accumulators; n-channel gated on d_needn
// Per node i: s4 contribution = di*(m_i + z_i)  [z = a1*dinv includes self-loop]
#define NCOPY 8
__global__ void __launch_bounds__(256) k_node3(const int* __restrict__ batch) {
    __shared__ float sacc[NCOPY][NG * 6];
    for (int j = threadIdx.x; j < NCOPY * NG * 6; j += blockDim.x)
        ((float*)sacc)[j] = 0.f;
    __syncthreads();
    GDC_WAIT();
    int needn = d_needn;
    int w = (threadIdx.x >> 5) & (NCOPY - 1);
    int stride = gridDim.x * blockDim.x;
    const float4 z4 = make_float4(0.f, 0.f, 0.f, 0.f);
    for (int i = blockIdx.x * blockDim.x + threadIdx.x; i < NN; i += stride) {
        float4 p = d_zp[i];
        float4 m = d_m[i];
        int g = batch[i];
        d_m[i] = z4;
        d_degx[i] = 0.f;
        float di = p.z;
        float2 z01 = __half22float2(*reinterpret_cast<half2*>(&p.x));
        float2 z23 = __half22float2(*reinterpret_cast<half2*>(&p.y));
        float* pp = &sacc[w][g * 6];
        atomicAdd(pp + 0, di * (m.x + z01.x));
        atomicAdd(pp + 1, di * (m.y + z01.y));
        atomicAdd(pp + 2, di * (m.z + z23.x));
        atomicAdd(pp + 3, di * (m.w + z23.y));
        if (needn) {
            float n = d_n[i];
            d_n[i] = 0.f;
            atomicAdd(pp + 4, di * (n + di));
        }
        atomicAdd(pp + 5, 1.0f);
    }
    __syncthreads();
    for (int j = threadIdx.x; j < NG * 6; j += blockDim.x) {
        float v = 0.f;
        #pragma unroll
        for (int k = 0; k < NCOPY; k++) v += sacc[k][j];
        int g = j / 6, c = j % 6;
        red1(&d_acc[g * 8 + c], v);
    }
    GDC_LAUNCH();
}

// Rank-7 tail: W0→W1→BN1→lin0→lin1→out as affine maps on the 7-vector
// c_g = (s4[0..3], ss, ng, 1). BN1 stats from the 7x7 second-moment matrix.
__global__ void __launch_bounds__(256) k_final(
        const float* __restrict__ W0, const float* __restrict__ b0,
        const float* __restrict__ W1, const float* __restrict__ b1,
        const float* __restrict__ bn1g, const float* __restrict__ bn1b,
        const float* __restrict__ l0W, const float* __restrict__ l0b,
        const float* __restrict__ l1W, const float* __restrict__ l1b,
        const float* __restrict__ oW, const float* __restrict__ ob,
        float* __restrict__ out) {
    __shared__ float sW[4096];
    __shared__ float sB[5][64];
    __shared__ float sA[2][7][68];
    __shared__ float sC[7][64];
    __shared__ float sS[7][7];
    __shared__ float swv[8];
    int t = threadIdx.x;

    for (int j = t; j < 4096; j += 256) sW[j] = W1[j];    // prelude
    if (t < 256) ((float*)sB)[t] = W0[t];
    if (t >= 192 && t < 256) sB[4][t - 192] = b0[t - 192];
    GDC_WAIT();

    if (t < 64) {
        float* acc = &d_acc[t * 8];
        sC[0][t] = acc[0];
        sC[1][t] = acc[1];
        sC[2][t] = acc[2];
        sC[3][t] = acc[3];
        sC[4][t] = acc[4];
        sC[5][t] = acc[5];
        sC[6][t] = 1.0f;
        #pragma unroll
        for (int c = 0; c < 8; c++) acc[c] = 0.f;
    }
    __syncthreads();

    for (int task = t; task < 320; task += 256) {
        int c = task >> 6, j = task & 63;
        float a = 0.f;
        #pragma unroll
        for (int k = 0; k < 64; k++) a += sB[c][k] * sW[k * 64 + j];
        sA[0][c][j] = a;
    }
    if (t < 64) {
        sA[0][5][t] = b1[t];
        sA[0][6][t] = 0.f;
    }
    if (t < 49) {
        int a = t / 7, b = t % 7;
        float s = 0.f;
        #pragma unroll
        for (int g = 0; g < 64; g++) s += sC[a][g] * sC[b][g];
        sS[a][b] = s;
    }
    __syncthreads();

    if (t < 64) {
        int j = t;
        float aj[7];
        #pragma unroll
        for (int c = 0; c < 7; c++) aj[c] = sA[0][c][j];
        float mu = 0.f;
        #pragma unroll
        for (int c = 0; c < 7; c++) mu += sS[c][6] * aj[c];
        mu *= (1.0f / 64.0f);
        float msq = 0.f;
        #pragma unroll
        for (int a = 0; a < 7; a++) {
            float inner = 0.f;
            #pragma unroll
            for (int b = 0; b < 7; b++) inner += sS[a][b] * aj[b];
            msq += aj[a] * inner;
        }
        msq *= (1.0f / 64.0f);
        float var = msq - mu * mu;
        float r = rsqrtf(var + EPS) * bn1g[j];
        #pragma unroll
        for (int c = 0; c < 7; c++) sA[0][c][j] = aj[c] * r;
        sA[0][6][j] += bn1b[j] - mu * r;
    }
    __syncthreads();

    for (int j = t; j < 4096; j += 256) sW[j] = l0W[j];
    __syncthreads();
    for (int task = t; task < 448; task += 256) {
        int c = task / 64, j = task & 63;
        float a = 0.f;
        #pragma unroll
        for (int k = 0; k < 64; k++) a += sA[0][c][k] * sW[k * 64 + j];
        if (c == 6) a += l0b[j];
        sA[1][c][j] = a;
    }
    __syncthreads();

    for (int j = t; j < 4096; j += 256) sW[j] = l1W[j];
    __syncthreads();
    for (int task = t; task < 448; task += 256) {
        int c = task / 64, j = task & 63;
        float a = 0.f;
        #pragma unroll
        for (int k = 0; k < 64; k++) a += sA[1][c][k] * sW[k * 64 + j];
        if (c == 6) a += l1b[j];
        sA[0][c][j] = a;
    }
    __syncthreads();

    if (t < 7) {
        float s = 0.f;
        #pragma unroll
        for (int j = 0; j < 64; j++) s += sA[0][t][j] * oW[j];
        swv[t] = s;
    }
    __syncthreads();
    if (t < 64) {
        float o = ob[0];
        #pragma unroll
        for (int c = 0; c < 7; c++) o += sC[c][t] * swv[c];
        out[t] = o;
    }
}

static void launch_pdl(const void* fn, dim3 grid, dim3 block, void** args) {
    cudaLaunchConfig_t cfg = {};
    cfg.gridDim = grid;
    cfg.blockDim = block;
    cfg.dynamicSmemBytes = 0;
    cfg.stream = 0;
    cudaLaunchAttribute at[1];
    at[0].id = cudaLaunchAttributeProgrammaticStreamSerialization;
    at[0].val.programmaticStreamSerializationAllowed = 1;
    cfg.attrs = at;
    cfg.numAttrs = 1;
    cudaLaunchKernelExC(&cfg, fn, args);
}

extern "C" void kernel_launch(void* const* d_in, const int* in_sizes, int n_in,
                              void* d_out, int out_size) {
    const float* x     = (const float*)d_in[0];
    const int*   ei    = (const int*)d_in[1];
    const int*   batch = (const int*)d_in[2];
    const float* bn0g = (const float*)d_in[3];
    const float* bn0b = (const float*)d_in[4];
    const float* W0   = (const float*)d_in[5];
    const float* b0   = (const float*)d_in[6];
    const float* W1   = (const float*)d_in[7];
    const float* b1   = (const float*)d_in[8];
    const float* bn1g = (const float*)d_in[9];
    const float* bn1b = (const float*)d_in[10];
    const float* l0W  = (const float*)d_in[11];
    const float* l0b  = (const float*)d_in[12];
    const float* l1W  = (const float*)d_in[13];
    const float* l1b  = (const float*)d_in[14];
    const float* oW   = (const float*)d_in[15];
    const float* ob   = (const float*)d_in[16];
    float* out = (float*)d_out;

    int et8 = NE / 8;
    dim3 b256(256);
    dim3 gE((et8 + 255) / 256);             // 1563
    dim3 gN2((NN / 2 + 255) / 256);         // 196

    { void* a[] = {(void*)&x, (void*)&ei};
      launch_pdl((const void*)k_pre, gE, b256, a); }
    { void* a[] = {(void*)&x, (void*)&bn0g, (void*)&bn0b, (void*)&b0};
      launch_pdl((const void*)k_node1, gN2, b256, a); }
    { void* a[] = {(void*)&ei};
      launch_pdl((const void*)k_edge1, gE, b256, a); }
    { void* a[] = {};
      launch_pdl((const void*)k_node2, gN2, b256, (void**)a); }
    { void* a[] = {(void*)&ei};
      launch_pdl((const void*)k_edge2, gE, b256, a); }
    { void* a[] = {(void*)&batch};
      launch_pdl((const void*)k_node3, dim3(148), b256, a); }
    { void* a[] = {(void*)&W0, (void*)&b0, (void*)&W1, (void*)&b1,
                   (void*)&bn1g, (void*)&bn1b, (void*)&l0W, (void*)&l0b,
                   (void*)&l1W, (void*)&l1b, (void*)&oW, (void*)&ob, (void*)&out};
      launch_pdl((const void*)k_final, dim3(1), b256, a); }
}

// round 14
// speedup vs baseline: 3.0294x; 1.0500x over previous
#include <cuda_runtime.h>
#include <cuda_fp16.h>

#define NN 100000
#define NE 3200000
#define NG 64
#define EPS 1e-5f

#define GDC_WAIT()   asm volatile("griddepcontrol.wait;" ::: "memory")
#define GDC_LAUNCH() asm volatile("griddepcontrol.launch_dependents;" ::: "memory")

// Scratch (__device__ globals). d_a1 fully overwritten by node1 each run;
// d_m/d_n/d_degx/d_acc are accumulators reset by the last kernel that reads them.
__device__ float4 d_y[NN];      // dinv*xn (also the self-loop seed)
__device__ float4 d_a1[NN];     // seeded y_i by node1, then += y_s by edge1
__device__ float4 d_zp[NN];     // packed {half2 z01, half2 z23, f32 dinv, pad}
__device__ float4 d_m[NN];      // layer2 v4 accumulator (reset in node3)
__device__ float  d_n[NN];      // layer2 scalar accumulator (reset in node3 when used)
__device__ float  d_degx[NN];   // degree-1 (reset in node3)
__device__ float  d_dinv[NN];
__device__ double d_sum[4];     // reset in node2
__device__ double d_sumsq[4];   // reset in node2
__device__ int    d_needn;      // 1 iff conv1 bias b0 nonzero
__device__ float  d_acc[NG * 8];// per graph: [0..3]=s4,[4]=ss,[5]=ng; reset in final

__device__ __forceinline__ void red4(float4* p, float a, float b, float c, float d) {
    asm volatile("red.global.add.v4.f32 [%0], {%1,%2,%3,%4};"
                 :: "l"(p), "f"(a), "f"(b), "f"(c), "f"(d) : "memory");
}
__device__ __forceinline__ void red4v(float4* p, float4 v) {
    asm volatile("red.global.add.v4.f32 [%0], {%1,%2,%3,%4};"
                 :: "l"(p), "f"(v.x), "f"(v.y), "f"(v.z), "f"(v.w) : "memory");
}
__device__ __forceinline__ void red1(float* p, float a) {
    asm volatile("red.global.add.f32 [%0], %1;" :: "l"(p), "f"(a) : "memory");
}

// Fused: degree accumulation (8 edges/thread) + BN0 statistics
__global__ void __launch_bounds__(256) k_pre(const float* __restrict__ x,
                                             const int* __restrict__ ei) {
    int t = blockIdx.x * blockDim.x + threadIdx.x;
    if (t < NE / 8) {
        const int4* dp = (const int4*)(ei + NE);
        int4 d0 = __ldg(&dp[2 * t]);
        int4 d1 = __ldg(&dp[2 * t + 1]);
        red1(&d_degx[d0.x], 1.0f);
        red1(&d_degx[d0.y], 1.0f);
        red1(&d_degx[d0.z], 1.0f);
        red1(&d_degx[d0.w], 1.0f);
        red1(&d_degx[d1.x], 1.0f);
        red1(&d_degx[d1.y], 1.0f);
        red1(&d_degx[d1.z], 1.0f);
        red1(&d_degx[d1.w], 1.0f);
    }
    if (blockIdx.x < 256) {
        int j0 = blockIdx.x * blockDim.x + threadIdx.x;
        int stride = 256 * blockDim.x;
        double s0 = 0, s1 = 0, s2 = 0, s3 = 0;
        double q0 = 0, q1 = 0, q2 = 0, q3 = 0;
        for (int j = j0; j < NN; j += stride) {
            float4 v = ((const float4*)x)[j];
            s0 += v.x; q0 += (double)v.x * v.x;
            s1 += v.y; q1 += (double)v.y * v.y;
            s2 += v.z; q2 += (double)v.z * v.z;
            s3 += v.w; q3 += (double)v.w * v.w;
        }
        #pragma unroll
        for (int o = 16; o > 0; o >>= 1) {
            s0 += __shfl_down_sync(0xffffffffu, s0, o);
            s1 += __shfl_down_sync(0xffffffffu, s1, o);
            s2 += __shfl_down_sync(0xffffffffu, s2, o);
            s3 += __shfl_down_sync(0xffffffffu, s3, o);
            q0 += __shfl_down_sync(0xffffffffu, q0, o);
            q1 += __shfl_down_sync(0xffffffffu, q1, o);
            q2 += __shfl_down_sync(0xffffffffu, q2, o);
            q3 += __shfl_down_sync(0xffffffffu, q3, o);
        }
        if ((threadIdx.x & 31) == 0) {
            atomicAdd(&d_sum[0], s0); atomicAdd(&d_sumsq[0], q0);
            atomicAdd(&d_sum[1], s1); atomicAdd(&d_sumsq[1], q1);
            atomicAdd(&d_sum[2], s2); atomicAdd(&d_sumsq[2], q2);
            atomicAdd(&d_sum[3], s3); atomicAdd(&d_sumsq[3], q3);
        }
    }
    GDC_LAUNCH();
}

// BN0 normalize + dinv + y; seeds d_a1 = y (self-loop term); 2 nodes/thread
__global__ void __launch_bounds__(256) k_node1(const float* __restrict__ x,
                                               const float* __restrict__ g0,
                                               const float* __restrict__ b0,
                                               const float* __restrict__ b0c) {
    __shared__ float sbn[12];
    int t = blockIdx.x * blockDim.x + threadIdx.x;
    int i0 = 2 * t, i1 = 2 * t + 1;
    bool a0 = (i0 < NN), a1 = (i1 < NN);
    float4 v0 = a0 ? ((const float4*)x)[i0] : make_float4(0, 0, 0, 0);  // prelude
    float4 v1 = a1 ? ((const float4*)x)[i1] : make_float4(0, 0, 0, 0);  // prelude
    GDC_WAIT();
    if (threadIdx.x == 0) {
        #pragma unroll
        for (int c = 0; c < 4; c++) {
            double m = d_sum[c] / (double)NN;
            double var = d_sumsq[c] / (double)NN - m * m;
            sbn[c] = (float)m;
            sbn[4 + c] = rsqrtf((float)var + EPS) * g0[c];
            sbn[8 + c] = b0[c];
        }
        if (blockIdx.x == 0) {
            float mx = 0.f;
            for (int j = 0; j < 64; j++) mx = fmaxf(mx, fabsf(b0c[j]));
            d_needn = (mx > 0.f) ? 1 : 0;
        }
    }
    __syncthreads();
    float dg0 = a0 ? d_degx[i0] : 0.f;
    float dg1 = a1 ? d_degx[i1] : 0.f;
    if (a0) {
        float di = rsqrtf(dg0 + 1.0f);
        float4 y;
        y.x = ((v0.x - sbn[0]) * sbn[4] + sbn[8]) * di;
        y.y = ((v0.y - sbn[1]) * sbn[5] + sbn[9]) * di;
        y.z = ((v0.z - sbn[2]) * sbn[6] + sbn[10]) * di;
        y.w = ((v0.w - sbn[3]) * sbn[7] + sbn[11]) * di;
        d_dinv[i0] = di;
        d_y[i0] = y;
        d_a1[i0] = y;      // self-loop seed: a1 = y_i + sum_s y_s
    }
    if (a1) {
        float di = rsqrtf(dg1 + 1.0f);
        float4 y;
        y.x = ((v1.x - sbn[0]) * sbn[4] + sbn[8]) * di;
        y.y = ((v1.y - sbn[1]) * sbn[5] + sbn[9]) * di;
        y.z = ((v1.z - sbn[2]) * sbn[6] + sbn[10]) * di;
        y.w = ((v1.w - sbn[3]) * sbn[7] + sbn[11]) * di;
        d_dinv[i1] = di;
        d_y[i1] = y;
        d_a1[i1] = y;
    }
    GDC_LAUNCH();
}

// a1[d] += y[s], 8 edges/thread; prelude: index loads
__global__ void __launch_bounds__(256) k_edge1(const int* __restrict__ ei) {
    int t = blockIdx.x * blockDim.x + threadIdx.x;
    bool act = (t < NE / 8);
    int tt = act ? t : 0;
    const int4* sp = (const int4*)ei;
    const int4* dp = (const int4*)(ei + NE);
    int4 s0 = __ldg(&sp[2 * tt]), s1 = __ldg(&sp[2 * tt + 1]);
    int4 d0 = __ldg(&dp[2 * tt]), d1 = __ldg(&dp[2 * tt + 1]);
    GDC_WAIT();
    if (act) {
        float4 y0 = __ldg(&d_y[s0.x]);
        float4 y1 = __ldg(&d_y[s0.y]);
        float4 y2 = __ldg(&d_y[s0.z]);
        float4 y3 = __ldg(&d_y[s0.w]);
        float4 y4 = __ldg(&d_y[s1.x]);
        float4 y5 = __ldg(&d_y[s1.y]);
        float4 y6 = __ldg(&d_y[s1.z]);
        float4 y7 = __ldg(&d_y[s1.w]);
        red4v(&d_a1[d0.x], y0);
        red4v(&d_a1[d0.y], y1);
        red4v(&d_a1[d0.z], y2);
        red4v(&d_a1[d0.w], y3);
        red4v(&d_a1[d1.x], y4);
        red4v(&d_a1[d1.y], y5);
        red4v(&d_a1[d1.z], y6);
        red4v(&d_a1[d1.w], y7);
    }
    GDC_LAUNCH();
}

// z = di^2 * a1, packed; 4 nodes/thread for MLP; resets BN sums
__global__ void __launch_bounds__(256) k_node2() {
    int t = blockIdx.x * blockDim.x + threadIdx.x;
    int base = 4 * t;
    float di[4];
    #pragma unroll
    for (int k = 0; k < 4; k++)
        di[k] = (base + k < NN) ? d_dinv[base + k] : 1.f;  // prelude
    GDC_WAIT();
    if (blockIdx.x == 0 && threadIdx.x < 4) {
        d_sum[threadIdx.x] = 0.0;
        d_sumsq[threadIdx.x] = 0.0;
    }
    float4 aa[4];
    #pragma unroll
    for (int k = 0; k < 4; k++)
        aa[k] = (base + k < NN) ? d_a1[base + k] : make_float4(0, 0, 0, 0);
    #pragma unroll
    for (int k = 0; k < 4; k++) {
        int i = base + k;
        if (i < NN) {
            float di2 = di[k] * di[k];
            half2 h01 = __floats2half2_rn(aa[k].x * di2, aa[k].y * di2);
            half2 h23 = __floats2half2_rn(aa[k].z * di2, aa[k].w * di2);
            float4 p;
            p.x = *reinterpret_cast<float*>(&h01);
            p.y = *reinterpret_cast<float*>(&h23);
            p.z = di[k];
            p.w = 0.f;
            d_zp[i] = p;
        }
    }
    GDC_LAUNCH();
}

// m[d] += z[s]; n-channel only when conv1 bias nonzero; prelude: index loads
__global__ void __launch_bounds__(256) k_edge2(const int* __restrict__ ei) {
    int t = blockIdx.x * blockDim.x + threadIdx.x;
    bool act = (t < NE / 8);
    int tt = act ? t : 0;
    const int4* sp = (const int4*)ei;
    const int4* dp = (const int4*)(ei + NE);
    int4 s0 = __ldg(&sp[2 * tt]), s1 = __ldg(&sp[2 * tt + 1]);
    int4 d0 = __ldg(&dp[2 * tt]), d1 = __ldg(&dp[2 * tt + 1]);
    GDC_WAIT();
    if (act) {
        int needn = d_needn;
        float4 p0 = __ldg(&d_zp[s0.x]);
        float4 p1 = __ldg(&d_zp[s0.y]);
        float4 p2 = __ldg(&d_zp[s0.z]);
        float4 p3 = __ldg(&d_zp[s0.w]);
        float4 p4 = __ldg(&d_zp[s1.x]);
        float4 p5 = __ldg(&d_zp[s1.y]);
        float4 p6 = __ldg(&d_zp[s1.z]);
        float4 p7 = __ldg(&d_zp[s1.w]);
        #define E2_M(p, dd) do {                                              \
            float2 _z01 = __half22float2(*reinterpret_cast<half2*>(&(p).x));  \
            float2 _z23 = __half22float2(*reinterpret_cast<half2*>(&(p).y));  \
            red4(&d_m[dd], _z01.x, _z01.y, _z23.x, _z23.y);                   \
        } while (0)
        E2_M(p0, d0.x);
        E2_M(p1, d0.y);
        E2_M(p2, d0.z);
        E2_M(p3, d0.w);
        E2_M(p4, d1.x);
        E2_M(p5, d1.y);
        E2_M(p6, d1.z);
        E2_M(p7, d1.w);
        #undef E2_M
        if (needn) {
            red1(&d_n[d0.x], p0.z);
            red1(&d_n[d0.y], p1.z);
            red1(&d_n[d0.z], p2.z);
            red1(&d_n[d0.w], p3.z);
            red1(&d_n[d1.x], p4.z);
            red1(&d_n[d1.y], p5.z);
            red1(&d_n[d1.z], p6.z);
            red1(&d_n[d1.w], p7.z);
        }
    }
    GDC_LAUNCH();
}

// per-graph reduction; resets node accumulators; n-channel gated on d_needn
#define NCOPY 8
__global__ void __launch_bounds__(256) k_node3(const int* __restrict__ batch) {
    __shared__ float sacc[NCOPY][NG * 6];
    for (int j = threadIdx.x; j < NCOPY * NG * 6; j += blockDim.x)
        ((float*)sacc)[j] = 0.f;
    __syncthreads();
    GDC_WAIT();
    int needn = d_needn;
    int w = (threadIdx.x >> 5) & (NCOPY - 1);
    int stride = gridDim.x * blockDim.x;
    const float4 z4 = make_float4(0.f, 0.f, 0.f, 0.f);
    for (int i = blockIdx.x * blockDim.x + threadIdx.x; i < NN; i += stride) {
        float4 p = d_zp[i];
        float4 m = d_m[i];
        int g = batch[i];
        d_m[i] = z4;
        d_degx[i] = 0.f;
        float di = p.z;
        float2 z01 = __half22float2(*reinterpret_cast<half2*>(&p.x));
        float2 z23 = __half22float2(*reinterpret_cast<half2*>(&p.y));
        float* pp = &sacc[w][g * 6];
        atomicAdd(pp + 0, di * (m.x + z01.x));
        atomicAdd(pp + 1, di * (m.y + z01.y));
        atomicAdd(pp + 2, di * (m.z + z23.x));
        atomicAdd(pp + 3, di * (m.w + z23.y));
        if (needn) {
            float n = d_n[i];
            d_n[i] = 0.f;
            atomicAdd(pp + 4, di * (n + di));
        }
        atomicAdd(pp + 5, 1.0f);
    }
    __syncthreads();
    for (int j = threadIdx.x; j < NG * 6; j += blockDim.x) {
        float v = 0.f;
        #pragma unroll
        for (int k = 0; k < NCOPY; k++) v += sacc[k][j];
        int g = j / 6, c = j % 6;
        red1(&d_acc[g * 8 + c], v);
    }
    GDC_LAUNCH();
}

// Rank-7 tail: W0→W1→BN1→lin0→lin1→out as affine maps on the 7-vector
// c_g = (s4[0..3], ss, ng, 1). BN1 stats from the 7x7 second-moment matrix.
__global__ void __launch_bounds__(256) k_final(
        const float* __restrict__ W0, const float* __restrict__ b0,
        const float* __restrict__ W1, const float* __restrict__ b1,
        const float* __restrict__ bn1g, const float* __restrict__ bn1b,
        const float* __restrict__ l0W, const float* __restrict__ l0b,
        const float* __restrict__ l1W, const float* __restrict__ l1b,
        const float* __restrict__ oW, const float* __restrict__ ob,
        float* __restrict__ out) {
    __shared__ float sW[4096];
    __shared__ float sB[5][64];
    __shared__ float sA[2][7][68];
    __shared__ float sC[7][64];
    __shared__ float sS[7][7];
    __shared__ float swv[8];
    int t = threadIdx.x;

    for (int j = t; j < 4096; j += 256) sW[j] = W1[j];    // prelude
    if (t < 256) ((float*)sB)[t] = W0[t];
    if (t >= 192 && t < 256) sB[4][t - 192] = b0[t - 192];
    GDC_WAIT();

    if (t < 64) {
        float* acc = &d_acc[t * 8];
        sC[0][t] = acc[0];
        sC[1][t] = acc[1];
        sC[2][t] = acc[2];
        sC[3][t] = acc[3];
        sC[4][t] = acc[4];
        sC[5][t] = acc[5];
        sC[6][t] = 1.0f;
        #pragma unroll
        for (int c = 0; c < 8; c++) acc[c] = 0.f;
    }
    __syncthreads();

    for (int task = t; task < 320; task += 256) {
        int c = task >> 6, j = task & 63;
        float a = 0.f;
        #pragma unroll
        for (int k = 0; k < 64; k++) a += sB[c][k] * sW[k * 64 + j];
        sA[0][c][j] = a;
    }
    if (t < 64) {
        sA[0][5][t] = b1[t];
        sA[0][6][t] = 0.f;
    }
    if (t < 49) {
        int a = t / 7, b = t % 7;
        float s = 0.f;
        #pragma unroll
        for (int g = 0; g < 64; g++) s += sC[a][g] * sC[b][g];
        sS[a][b] = s;
    }
    __syncthreads();

    if (t < 64) {
        int j = t;
        float aj[7];
        #pragma unroll
        for (int c = 0; c < 7; c++) aj[c] = sA[0][c][j];
        float mu = 0.f;
        #pragma unroll
        for (int c = 0; c < 7; c++) mu += sS[c][6] * aj[c];
        mu *= (1.0f / 64.0f);
        float msq = 0.f;
        #pragma unroll
        for (int a = 0; a < 7; a++) {
            float inner = 0.f;
            #pragma unroll
            for (int b = 0; b < 7; b++) inner += sS[a][b] * aj[b];
            msq += aj[a] * inner;
        }
        msq *= (1.0f / 64.0f);
        float var = msq - mu * mu;
        float r = rsqrtf(var + EPS) * bn1g[j];
        #pragma unroll
        for (int c = 0; c < 7; c++) sA[0][c][j] = aj[c] * r;
        sA[0][6][j] += bn1b[j] - mu * r;
    }
    __syncthreads();

    for (int j = t; j < 4096; j += 256) sW[j] = l0W[j];
    __syncthreads();
    for (int task = t; task < 448; task += 256) {
        int c = task / 64, j = task & 63;
        float a = 0.f;
        #pragma unroll
        for (int k = 0; k < 64; k++) a += sA[0][c][k] * sW[k * 64 + j];
        if (c == 6) a += l0b[j];
        sA[1][c][j] = a;
    }
    __syncthreads();

    for (int j = t; j < 4096; j += 256) sW[j] = l1W[j];
    __syncthreads();
    for (int task = t; task < 448; task += 256) {
        int c = task / 64, j = task & 63;
        float a = 0.f;
        #pragma unroll
        for (int k = 0; k < 64; k++) a += sA[1][c][k] * sW[k * 64 + j];
        if (c == 6) a += l1b[j];
        sA[0][c][j] = a;
    }
    __syncthreads();

    if (t < 7) {
        float s = 0.f;
        #pragma unroll
        for (int j = 0; j < 64; j++) s += sA[0][t][j] * oW[j];
        swv[t] = s;
    }
    __syncthreads();
    if (t < 64) {
        float o = ob[0];
        #pragma unroll
        for (int c = 0; c < 7; c++) o += sC[c][t] * swv[c];
        out[t] = o;
    }
}

static void launch_pdl(const void* fn, dim3 grid, dim3 block, void** args) {
    cudaLaunchConfig_t cfg = {};
    cfg.gridDim = grid;
    cfg.blockDim = block;
    cfg.dynamicSmemBytes = 0;
    cfg.stream = 0;
    cudaLaunchAttribute at[1];
    at[0].id = cudaLaunchAttributeProgrammaticStreamSerialization;
    at[0].val.programmaticStreamSerializationAllowed = 1;
    cfg.attrs = at;
    cfg.numAttrs = 1;
    cudaLaunchKernelExC(&cfg, fn, args);
}

extern "C" void kernel_launch(void* const* d_in, const int* in_sizes, int n_in,
                              void* d_out, int out_size) {
    const float* x     = (const float*)d_in[0];
    const int*   ei    = (const int*)d_in[1];
    const int*   batch = (const int*)d_in[2];
    const float* bn0g = (const float*)d_in[3];
    const float* bn0b = (const float*)d_in[4];
    const float* W0   = (const float*)d_in[5];
    const float* b0   = (const float*)d_in[6];
    const float* W1   = (const float*)d_in[7];
    const float* b1   = (const float*)d_in[8];
    const float* bn1g = (const float*)d_in[9];
    const float* bn1b = (const float*)d_in[10];
    const float* l0W  = (const float*)d_in[11];
    const float* l0b  = (const float*)d_in[12];
    const float* l1W  = (const float*)d_in[13];
    const float* l1b  = (const float*)d_in[14];
    const float* oW   = (const float*)d_in[15];
    const float* ob   = (const float*)d_in[16];
    float* out = (float*)d_out;

    int et8 = NE / 8;
    dim3 b256(256);
    dim3 gE((et8 + 255) / 256);             // 1563
    dim3 gN2((NN / 2 + 255) / 256);         // 196
    dim3 gN4((NN / 4 + 255) / 256);         // 98

    { void* a[] = {(void*)&x, (void*)&ei};
      launch_pdl((const void*)k_pre, gE, b256, a); }
    { void* a[] = {(void*)&x, (void*)&bn0g, (void*)&bn0b, (void*)&b0};
      launch_pdl((const void*)k_node1, gN2, b256, a); }
    { void* a[] = {(void*)&ei};
      launch_pdl((const void*)k_edge1, gE, b256, a); }
    { void* a[] = {};
      launch_pdl((const void*)k_node2, gN4, b256, (void**)a); }
    { void* a[] = {(void*)&ei};
      launch_pdl((const void*)k_edge2, gE, b256, a); }
    { void* a[] = {(void*)&batch};
      launch_pdl((const void*)k_node3, dim3(296), b256, a); }
    { void* a[] = {(void*)&W0, (void*)&b0, (void*)&W1, (void*)&b1,
                   (void*)&bn1g, (void*)&bn1b, (void*)&l0W, (void*)&l0b,
                   (void*)&l1W, (void*)&l1b, (void*)&oW, (void*)&ob, (void*)&out};
      launch_pdl((const void*)k_final, dim3(1), b256, a); }
}

// round 15
// speedup vs baseline: 3.3255x; 1.0977x over previous
#include <cuda_runtime.h>
#include <cuda_fp16.h>

#define NN 100000
#define NE 3200000
#define NG 64
#define EPS 1e-5f

#define GDC_WAIT()   asm volatile("griddepcontrol.wait;" ::: "memory")
#define GDC_LAUNCH() asm volatile("griddepcontrol.launch_dependents;" ::: "memory")

// Scratch (__device__ globals). d_a1 fully overwritten by node1 each run;
// d_m/d_n/d_degx/d_acc are accumulators reset by the last kernel that reads them.
__device__ float4 d_y[NN];      // dinv*xn (also the self-loop seed)
__device__ float4 d_a1[NN];     // seeded y_i by node1, then += y_s by edge1
__device__ float4 d_zp[NN];     // packed {half2 z01, half2 z23, f32 dinv, pad}
__device__ float4 d_m[NN];      // layer2 v4 accumulator (reset in node3)
__device__ float  d_n[NN];      // layer2 scalar accumulator (reset in node3 when used)
__device__ float  d_degx[NN];   // degree-1 (reset in node3)
__device__ float  d_dinv[NN];
__device__ double d_sum[4];     // reset in node2
__device__ double d_sumsq[4];   // reset in node2
__device__ int    d_needn;      // 1 iff conv1 bias b0 nonzero
__device__ float  d_acc[NG * 8];// per graph: [0..3]=s4,[4]=ss,[5]=ng; reset in final

__device__ __forceinline__ void red4(float4* p, float a, float b, float c, float d) {
    asm volatile("red.global.add.v4.f32 [%0], {%1,%2,%3,%4};"
                 :: "l"(p), "f"(a), "f"(b), "f"(c), "f"(d) : "memory");
}
__device__ __forceinline__ void red4v(float4* p, float4 v) {
    asm volatile("red.global.add.v4.f32 [%0], {%1,%2,%3,%4};"
                 :: "l"(p), "f"(v.x), "f"(v.y), "f"(v.z), "f"(v.w) : "memory");
}
__device__ __forceinline__ void red1(float* p, float a) {
    asm volatile("red.global.add.f32 [%0], %1;" :: "l"(p), "f"(a) : "memory");
}

// Fused: degree accumulation (8 edges/thread) + BN0 statistics
__global__ void __launch_bounds__(256) k_pre(const float* __restrict__ x,
                                             const int* __restrict__ ei) {
    int t = blockIdx.x * blockDim.x + threadIdx.x;
    if (t < NE / 8) {
        const int4* dp = (const int4*)(ei + NE);
        int4 d0 = __ldg(&dp[2 * t]);
        int4 d1 = __ldg(&dp[2 * t + 1]);
        red1(&d_degx[d0.x], 1.0f);
        red1(&d_degx[d0.y], 1.0f);
        red1(&d_degx[d0.z], 1.0f);
        red1(&d_degx[d0.w], 1.0f);
        red1(&d_degx[d1.x], 1.0f);
        red1(&d_degx[d1.y], 1.0f);
        red1(&d_degx[d1.z], 1.0f);
        red1(&d_degx[d1.w], 1.0f);
    }
    if (blockIdx.x < 256) {
        int j0 = blockIdx.x * blockDim.x + threadIdx.x;
        int stride = 256 * blockDim.x;
        double s0 = 0, s1 = 0, s2 = 0, s3 = 0;
        double q0 = 0, q1 = 0, q2 = 0, q3 = 0;
        for (int j = j0; j < NN; j += stride) {
            float4 v = ((const float4*)x)[j];
            s0 += v.x; q0 += (double)v.x * v.x;
            s1 += v.y; q1 += (double)v.y * v.y;
            s2 += v.z; q2 += (double)v.z * v.z;
            s3 += v.w; q3 += (double)v.w * v.w;
        }
        #pragma unroll
        for (int o = 16; o > 0; o >>= 1) {
            s0 += __shfl_down_sync(0xffffffffu, s0, o);
            s1 += __shfl_down_sync(0xffffffffu, s1, o);
            s2 += __shfl_down_sync(0xffffffffu, s2, o);
            s3 += __shfl_down_sync(0xffffffffu, s3, o);
            q0 += __shfl_down_sync(0xffffffffu, q0, o);
            q1 += __shfl_down_sync(0xffffffffu, q1, o);
            q2 += __shfl_down_sync(0xffffffffu, q2, o);
            q3 += __shfl_down_sync(0xffffffffu, q3, o);
        }
        if ((threadIdx.x & 31) == 0) {
            atomicAdd(&d_sum[0], s0); atomicAdd(&d_sumsq[0], q0);
            atomicAdd(&d_sum[1], s1); atomicAdd(&d_sumsq[1], q1);
            atomicAdd(&d_sum[2], s2); atomicAdd(&d_sumsq[2], q2);
            atomicAdd(&d_sum[3], s3); atomicAdd(&d_sumsq[3], q3);
        }
    }
    GDC_LAUNCH();
}

// BN0 normalize + dinv + y; seeds d_a1 = y (self-loop term); 2 nodes/thread
__global__ void __launch_bounds__(256) k_node1(const float* __restrict__ x,
                                               const float* __restrict__ g0,
                                               const float* __restrict__ b0,
                                               const float* __restrict__ b0c) {
    __shared__ float sbn[12];
    int t = blockIdx.x * blockDim.x + threadIdx.x;
    int i0 = 2 * t, i1 = 2 * t + 1;
    bool a0 = (i0 < NN), a1 = (i1 < NN);
    float4 v0 = a0 ? ((const float4*)x)[i0] : make_float4(0, 0, 0, 0);  // prelude
    float4 v1 = a1 ? ((const float4*)x)[i1] : make_float4(0, 0, 0, 0);  // prelude
    GDC_WAIT();
    if (threadIdx.x == 0) {
        #pragma unroll
        for (int c = 0; c < 4; c++) {
            double m = d_sum[c] / (double)NN;
            double var = d_sumsq[c] / (double)NN - m * m;
            sbn[c] = (float)m;
            sbn[4 + c] = rsqrtf((float)var + EPS) * g0[c];
            sbn[8 + c] = b0[c];
        }
        if (blockIdx.x == 0) {
            float mx = 0.f;
            for (int j = 0; j < 64; j++) mx = fmaxf(mx, fabsf(b0c[j]));
            d_needn = (mx > 0.f) ? 1 : 0;
        }
    }
    __syncthreads();
    float dg0 = a0 ? d_degx[i0] : 0.f;
    float dg1 = a1 ? d_degx[i1] : 0.f;
    if (a0) {
        float di = rsqrtf(dg0 + 1.0f);
        float4 y;
        y.x = ((v0.x - sbn[0]) * sbn[4] + sbn[8]) * di;
        y.y = ((v0.y - sbn[1]) * sbn[5] + sbn[9]) * di;
        y.z = ((v0.z - sbn[2]) * sbn[6] + sbn[10]) * di;
        y.w = ((v0.w - sbn[3]) * sbn[7] + sbn[11]) * di;
        d_dinv[i0] = di;
        d_y[i0] = y;
        d_a1[i0] = y;      // self-loop seed: a1 = y_i + sum_s y_s
    }
    if (a1) {
        float di = rsqrtf(dg1 + 1.0f);
        float4 y;
        y.x = ((v1.x - sbn[0]) * sbn[4] + sbn[8]) * di;
        y.y = ((v1.y - sbn[1]) * sbn[5] + sbn[9]) * di;
        y.z = ((v1.z - sbn[2]) * sbn[6] + sbn[10]) * di;
        y.w = ((v1.w - sbn[3]) * sbn[7] + sbn[11]) * di;
        d_dinv[i1] = di;
        d_y[i1] = y;
        d_a1[i1] = y;
    }
    GDC_LAUNCH();
}

// a1[d] += y[s], 8 edges/thread; prelude: index loads
__global__ void __launch_bounds__(256) k_edge1(const int* __restrict__ ei) {
    int t = blockIdx.x * blockDim.x + threadIdx.x;
    bool act = (t < NE / 8);
    int tt = act ? t : 0;
    const int4* sp = (const int4*)ei;
    const int4* dp = (const int4*)(ei + NE);
    int4 s0 = __ldg(&sp[2 * tt]), s1 = __ldg(&sp[2 * tt + 1]);
    int4 d0 = __ldg(&dp[2 * tt]), d1 = __ldg(&dp[2 * tt + 1]);
    GDC_WAIT();
    if (act) {
        float4 y0 = __ldg(&d_y[s0.x]);
        float4 y1 = __ldg(&d_y[s0.y]);
        float4 y2 = __ldg(&d_y[s0.z]);
        float4 y3 = __ldg(&d_y[s0.w]);
        float4 y4 = __ldg(&d_y[s1.x]);
        float4 y5 = __ldg(&d_y[s1.y]);
        float4 y6 = __ldg(&d_y[s1.z]);
        float4 y7 = __ldg(&d_y[s1.w]);
        red4v(&d_a1[d0.x], y0);
        red4v(&d_a1[d0.y], y1);
        red4v(&d_a1[d0.z], y2);
        red4v(&d_a1[d0.w], y3);
        red4v(&d_a1[d1.x], y4);
        red4v(&d_a1[d1.y], y5);
        red4v(&d_a1[d1.z], y6);
        red4v(&d_a1[d1.w], y7);
    }
    GDC_LAUNCH();
}

// z = di^2 * a1, packed; 2 nodes/thread; resets BN sums
__global__ void __launch_bounds__(256) k_node2() {
    int t = blockIdx.x * blockDim.x + threadIdx.x;
    int i0 = 2 * t, i1 = 2 * t + 1;
    bool a0 = (i0 < NN), b1 = (i1 < NN);
    float di0 = a0 ? d_dinv[i0] : 1.f;   // prelude (node1 is 2 kernels back)
    float di1 = b1 ? d_dinv[i1] : 1.f;
    GDC_WAIT();
    if (blockIdx.x == 0 && threadIdx.x < 4) {
        d_sum[threadIdx.x] = 0.0;
        d_sumsq[threadIdx.x] = 0.0;
    }
    float4 aa0 = a0 ? d_a1[i0] : make_float4(0, 0, 0, 0);
    float4 aa1 = b1 ? d_a1[i1] : make_float4(0, 0, 0, 0);
    if (a0) {
        float di2 = di0 * di0;
        half2 h01 = __floats2half2_rn(aa0.x * di2, aa0.y * di2);
        half2 h23 = __floats2half2_rn(aa0.z * di2, aa0.w * di2);
        float4 p;
        p.x = *reinterpret_cast<float*>(&h01);
        p.y = *reinterpret_cast<float*>(&h23);
        p.z = di0;
        p.w = 0.f;
        d_zp[i0] = p;
    }
    if (b1) {
        float di2 = di1 * di1;
        half2 h01 = __floats2half2_rn(aa1.x * di2, aa1.y * di2);
        half2 h23 = __floats2half2_rn(aa1.z * di2, aa1.w * di2);
        float4 p;
        p.x = *reinterpret_cast<float*>(&h01);
        p.y = *reinterpret_cast<float*>(&h23);
        p.z = di1;
        p.w = 0.f;
        d_zp[i1] = p;
    }
    GDC_LAUNCH();
}

// m[d] += z[s]; n-channel only when conv1 bias nonzero; prelude: index loads
__global__ void __launch_bounds__(256) k_edge2(const int* __restrict__ ei) {
    int t = blockIdx.x * blockDim.x + threadIdx.x;
    bool act = (t < NE / 8);
    int tt = act ? t : 0;
    const int4* sp = (const int4*)ei;
    const int4* dp = (const int4*)(ei + NE);
    int4 s0 = __ldg(&sp[2 * tt]), s1 = __ldg(&sp[2 * tt + 1]);
    int4 d0 = __ldg(&dp[2 * tt]), d1 = __ldg(&dp[2 * tt + 1]);
    GDC_WAIT();
    if (act) {
        int needn = d_needn;
        float4 p0 = __ldg(&d_zp[s0.x]);
        float4 p1 = __ldg(&d_zp[s0.y]);
        float4 p2 = __ldg(&d_zp[s0.z]);
        float4 p3 = __ldg(&d_zp[s0.w]);
        float4 p4 = __ldg(&d_zp[s1.x]);
        float4 p5 = __ldg(&d_zp[s1.y]);
        float4 p6 = __ldg(&d_zp[s1.z]);
        float4 p7 = __ldg(&d_zp[s1.w]);
        #define E2_M(p, dd) do {                                              \
            float2 _z01 = __half22float2(*reinterpret_cast<half2*>(&(p).x));  \
            float2 _z23 = __half22float2(*reinterpret_cast<half2*>(&(p).y));  \
            red4(&d_m[dd], _z01.x, _z01.y, _z23.x, _z23.y);                   \
        } while (0)
        E2_M(p0, d0.x);
        E2_M(p1, d0.y);
        E2_M(p2, d0.z);
        E2_M(p3, d0.w);
        E2_M(p4, d1.x);
        E2_M(p5, d1.y);
        E2_M(p6, d1.z);
        E2_M(p7, d1.w);
        #undef E2_M
        if (needn) {
            red1(&d_n[d0.x], p0.z);
            red1(&d_n[d0.y], p1.z);
            red1(&d_n[d0.z], p2.z);
            red1(&d_n[d0.w], p3.z);
            red1(&d_n[d1.x], p4.z);
            red1(&d_n[d1.y], p5.z);
            red1(&d_n[d1.z], p6.z);
            red1(&d_n[d1.w], p7.z);
        }
    }
    GDC_LAUNCH();
}

// per-graph reduction; batch is SORTED, so most warps are graph-uniform:
// butterfly-reduce in registers, lane 0 does the atomics. Fallback for
// boundary warps. Resets node accumulators.
#define NCOPY 8
__global__ void __launch_bounds__(256) k_node3(const int* __restrict__ batch) {
    __shared__ float sacc[NCOPY][NG * 6];
    for (int j = threadIdx.x; j < NCOPY * NG * 6; j += blockDim.x)
        ((float*)sacc)[j] = 0.f;
    __syncthreads();
    GDC_WAIT();
    int needn = d_needn;
    int w = (threadIdx.x >> 5) & (NCOPY - 1);
    int lane = threadIdx.x & 31;
    int stride = gridDim.x * blockDim.x;
    const float4 z4 = make_float4(0.f, 0.f, 0.f, 0.f);
    for (int i = blockIdx.x * blockDim.x + threadIdx.x; i < NN; i += stride) {
        float4 p = d_zp[i];
        float4 m = d_m[i];
        int g = batch[i];
        d_m[i] = z4;
        d_degx[i] = 0.f;
        float di = p.z;
        float2 z01 = __half22float2(*reinterpret_cast<half2*>(&p.x));
        float2 z23 = __half22float2(*reinterpret_cast<half2*>(&p.y));
        float v0 = di * (m.x + z01.x);
        float v1 = di * (m.y + z01.y);
        float v2 = di * (m.z + z23.x);
        float v3 = di * (m.w + z23.y);
        float v4 = 0.f;
        if (needn) {
            float n = d_n[i];
            d_n[i] = 0.f;
            v4 = di * (n + di);
        }
        int g0 = __shfl_sync(0xffffffffu, g, 0);
        bool uniform = __all_sync(0xffffffffu, g == g0);
        if (uniform) {
            #pragma unroll
            for (int o = 16; o > 0; o >>= 1) {
                v0 += __shfl_down_sync(0xffffffffu, v0, o);
                v1 += __shfl_down_sync(0xffffffffu, v1, o);
                v2 += __shfl_down_sync(0xffffffffu, v2, o);
                v3 += __shfl_down_sync(0xffffffffu, v3, o);
                v4 += __shfl_down_sync(0xffffffffu, v4, o);
            }
            if (lane == 0) {
                float* pp = &sacc[w][g0 * 6];
                atomicAdd(pp + 0, v0);
                atomicAdd(pp + 1, v1);
                atomicAdd(pp + 2, v2);
                atomicAdd(pp + 3, v3);
                if (needn) atomicAdd(pp + 4, v4);
                atomicAdd(pp + 5, 32.0f);
            }
        } else {
            float* pp = &sacc[w][g * 6];
            atomicAdd(pp + 0, v0);
            atomicAdd(pp + 1, v1);
            atomicAdd(pp + 2, v2);
            atomicAdd(pp + 3, v3);
            if (needn) atomicAdd(pp + 4, v4);
            atomicAdd(pp + 5, 1.0f);
        }
    }
    __syncthreads();
    for (int j = threadIdx.x; j < NG * 6; j += blockDim.x) {
        float v = 0.f;
        #pragma unroll
        for (int k = 0; k < NCOPY; k++) v += sacc[k][j];
        int g = j / 6, c = j % 6;
        red1(&d_acc[g * 8 + c], v);
    }
    GDC_LAUNCH();
}

// Rank-7 tail: W0→W1→BN1→lin0→lin1→out as affine maps on the 7-vector
// c_g = (s4[0..3], ss, ng, 1). BN1 stats from the 7x7 second-moment matrix.
__global__ void __launch_bounds__(256) k_final(
        const float* __restrict__ W0, const float* __restrict__ b0,
        const float* __restrict__ W1, const float* __restrict__ b1,
        const float* __restrict__ bn1g, const float* __restrict__ bn1b,
        const float* __restrict__ l0W, const float* __restrict__ l0b,
        const float* __restrict__ l1W, const float* __restrict__ l1b,
        const float* __restrict__ oW, const float* __restrict__ ob,
        float* __restrict__ out) {
    __shared__ float sW[4096];
    __shared__ float sB[5][64];
    __shared__ float sA[2][7][68];
    __shared__ float sC[7][64];
    __shared__ float sS[7][7];
    __shared__ float swv[8];
    int t = threadIdx.x;

    for (int j = t; j < 4096; j += 256) sW[j] = W1[j];    // prelude
    if (t < 256) ((float*)sB)[t] = W0[t];
    if (t >= 192 && t < 256) sB[4][t - 192] = b0[t - 192];
    GDC_WAIT();

    if (t < 64) {
        float* acc = &d_acc[t * 8];
        sC[0][t] = acc[0];
        sC[1][t] = acc[1];
        sC[2][t] = acc[2];
        sC[3][t] = acc[3];
        sC[4][t] = acc[4];
        sC[5][t] = acc[5];
        sC[6][t] = 1.0f;
        #pragma unroll
        for (int c = 0; c < 8; c++) acc[c] = 0.f;
    }
    __syncthreads();

    for (int task = t; task < 320; task += 256) {
        int c = task >> 6, j = task & 63;
        float a = 0.f;
        #pragma unroll
        for (int k = 0; k < 64; k++) a += sB[c][k] * sW[k * 64 + j];
        sA[0][c][j] = a;
    }
    if (t < 64) {
        sA[0][5][t] = b1[t];
        sA[0][6][t] = 0.f;
    }
    if (t < 49) {
        int a = t / 7, b = t % 7;
        float s = 0.f;
        #pragma unroll
        for (int g = 0; g < 64; g++) s += sC[a][g] * sC[b][g];
        sS[a][b] = s;
    }
    __syncthreads();

    if (t < 64) {
        int j = t;
        float aj[7];
        #pragma unroll
        for (int c = 0; c < 7; c++) aj[c] = sA[0][c][j];
        float mu = 0.f;
        #pragma unroll
        for (int c = 0; c < 7; c++) mu += sS[c][6] * aj[c];
        mu *= (1.0f / 64.0f);
        float msq = 0.f;
        #pragma unroll
        for (int a = 0; a < 7; a++) {
            float inner = 0.f;
            #pragma unroll
            for (int b = 0; b < 7; b++) inner += sS[a][b] * aj[b];
            msq += aj[a] * inner;
        }
        msq *= (1.0f / 64.0f);
        float var = msq - mu * mu;
        float r = rsqrtf(var + EPS) * bn1g[j];
        #pragma unroll
        for (int c = 0; c < 7; c++) sA[0][c][j] = aj[c] * r;
        sA[0][6][j] += bn1b[j] - mu * r;
    }
    __syncthreads();

    for (int j = t; j < 4096; j += 256) sW[j] = l0W[j];
    __syncthreads();
    for (int task = t; task < 448; task += 256) {
        int c = task / 64, j = task & 63;
        float a = 0.f;
        #pragma unroll
        for (int k = 0; k < 64; k++) a += sA[0][c][k] * sW[k * 64 + j];
        if (c == 6) a += l0b[j];
        sA[1][c][j] = a;
    }
    __syncthreads();

    for (int j = t; j < 4096; j += 256) sW[j] = l1W[j];
    __syncthreads();
    for (int task = t; task < 448; task += 256) {
        int c = task / 64, j = task & 63;
        float a = 0.f;
        #pragma unroll
        for (int k = 0; k < 64; k++) a += sA[1][c][k] * sW[k * 64 + j];
        if (c == 6) a += l1b[j];
        sA[0][c][j] = a;
    }
    __syncthreads();

    if (t < 7) {
        float s = 0.f;
        #pragma unroll
        for (int j = 0; j < 64; j++) s += sA[0][t][j] * oW[j];
        swv[t] = s;
    }
    __syncthreads();
    if (t < 64) {
        float o = ob[0];
        #pragma unroll
        for (int c = 0; c < 7; c++) o += sC[c][t] * swv[c];
        out[t] = o;
    }
}

static void launch_pdl(const void* fn, dim3 grid, dim3 block, void** args) {
    cudaLaunchConfig_t cfg = {};
    cfg.gridDim = grid;
    cfg.blockDim = block;
    cfg.dynamicSmemBytes = 0;
    cfg.stream = 0;
    cudaLaunchAttribute at[1];
    at[0].id = cudaLaunchAttributeProgrammaticStreamSerialization;
    at[0].val.programmaticStreamSerializationAllowed = 1;
    cfg.attrs = at;
    cfg.numAttrs = 1;
    cudaLaunchKernelExC(&cfg, fn, args);
}

extern "C" void kernel_launch(void* const* d_in, const int* in_sizes, int n_in,
                              void* d_out, int out_size) {
    const float* x     = (const float*)d_in[0];
    const int*   ei    = (const int*)d_in[1];
    const int*   batch = (const int*)d_in[2];
    const float* bn0g = (const float*)d_in[3];
    const float* bn0b = (const float*)d_in[4];
    const float* W0   = (const float*)d_in[5];
    const float* b0   = (const float*)d_in[6];
    const float* W1   = (const float*)d_in[7];
    const float* b1   = (const float*)d_in[8];
    const float* bn1g = (const float*)d_in[9];
    const float* bn1b = (const float*)d_in[10];
    const float* l0W  = (const float*)d_in[11];
    const float* l0b  = (const float*)d_in[12];
    const float* l1W  = (const float*)d_in[13];
    const float* l1b  = (const float*)d_in[14];
    const float* oW   = (const float*)d_in[15];
    const float* ob   = (const float*)d_in[16];
    float* out = (float*)d_out;

    int et8 = NE / 8;
    dim3 b256(256);
    dim3 gE((et8 + 255) / 256);             // 1563
    dim3 gN2((NN / 2 + 255) / 256);         // 196

    { void* a[] = {(void*)&x, (void*)&ei};
      launch_pdl((const void*)k_pre, gE, b256, a); }
    { void* a[] = {(void*)&x, (void*)&bn0g, (void*)&bn0b, (void*)&b0};
      launch_pdl((const void*)k_node1, gN2, b256, a); }
    { void* a[] = {(void*)&ei};
      launch_pdl((const void*)k_edge1, gE, b256, a); }
    { void* a[] = {};
      launch_pdl((const void*)k_node2, gN2, b256, (void**)a); }
    { void* a[] = {(void*)&ei};
      launch_pdl((const void*)k_edge2, gE, b256, a); }
    { void* a[] = {(void*)&batch};
      launch_pdl((const void*)k_node3, dim3(296), b256, a); }
    { void* a[] = {(void*)&W0, (void*)&b0, (void*)&W1, (void*)&b1,
                   (void*)&bn1g, (void*)&bn1b, (void*)&l0W, (void*)&l0b,
                   (void*)&l1W, (void*)&l1b, (void*)&oW, (void*)&ob, (void*)&out};
      launch_pdl((const void*)k_final, dim3(1), b256, a); }
}